// round 8
// baseline (speedup 1.0000x reference)
#include <cuda_runtime.h>
#include <cuda_bf16.h>

#define SCALING 0.17677669529663687f

// ---------------------------------------------------------------------------
// Scratch (static device globals — allowed; no runtime allocation)
// ---------------------------------------------------------------------------
__device__ __nv_bfloat16 g_projh[9][32][1024][32];  // bf16 hi planes
__device__ __nv_bfloat16 g_projl[9][32][1024][32];  // bf16 lo planes
__device__ float g_v[32][1024][32];                 // V fp32 (AV)
__device__ float g_mask[32][1024 * 1024];           // local_mask
__device__ __nv_bfloat16 g_xh[3][1048576], g_xl[3][1048576];  // X hi/lo
__device__ __nv_bfloat16 g_wh[589824], g_wl[589824];          // in_proj_w hi/lo
__device__ __nv_bfloat16 g_owh[65536], g_owl[65536];          // out_w hi/lo
__device__ __nv_bfloat16 g_attnh[1048576], g_attnl[1048576];  // attn hi/lo

// ---------------------------------------------------------------------------
// mma.sync m16n8k16 bf16 (HMMA), D/C fp32
// ---------------------------------------------------------------------------
__device__ __forceinline__ void mma_bf16(
    float& d0, float& d1, float& d2, float& d3,
    unsigned a0, unsigned a1, unsigned a2, unsigned a3,
    unsigned b0, unsigned b1)
{
    asm volatile(
        "mma.sync.aligned.m16n8k16.row.col.f32.bf16.bf16.f32 "
        "{%0,%1,%2,%3}, {%4,%5,%6,%7}, {%8,%9}, {%0,%1,%2,%3};\n"
        : "+f"(d0), "+f"(d1), "+f"(d2), "+f"(d3)
        : "r"(a0), "r"(a1), "r"(a2), "r"(a3), "r"(b0), "r"(b1));
}
__device__ __forceinline__ unsigned ldu32(const __nv_bfloat16* p) {
    return *(const unsigned*)p;
}

// ---------------------------------------------------------------------------
// warp helpers (R6-proven)
// ---------------------------------------------------------------------------
__device__ __forceinline__ void warp_iscan2(float& a, float& b, int lane) {
    #pragma unroll
    for (int o = 1; o < 32; o <<= 1) {
        float ua = __shfl_up_sync(0xffffffffu, a, o);
        float ub = __shfl_up_sync(0xffffffffu, b, o);
        if (lane >= o) { a += ua; b += ub; }
    }
}
__device__ __forceinline__ void warp_softmax_row2(float* r0, float* r1, int lane) {
    float m0 = -1e30f, m1 = -1e30f;
    #pragma unroll
    for (int q = 0; q < 32; q++) {
        m0 = fmaxf(m0, r0[q * 32 + lane]);
        m1 = fmaxf(m1, r1[q * 32 + lane]);
    }
    #pragma unroll
    for (int o = 16; o; o >>= 1) {
        m0 = fmaxf(m0, __shfl_xor_sync(0xffffffffu, m0, o));
        m1 = fmaxf(m1, __shfl_xor_sync(0xffffffffu, m1, o));
    }
    float s0 = 0.f, s1 = 0.f;
    #pragma unroll
    for (int q = 0; q < 32; q++) {
        float e0 = __expf(r0[q * 32 + lane] - m0);
        float e1 = __expf(r1[q * 32 + lane] - m1);
        r0[q * 32 + lane] = e0;
        r1[q * 32 + lane] = e1;
        s0 += e0; s1 += e1;
    }
    #pragma unroll
    for (int o = 16; o; o >>= 1) {
        s0 += __shfl_xor_sync(0xffffffffu, s0, o);
        s1 += __shfl_xor_sync(0xffffffffu, s1, o);
    }
    float i0 = 1.0f / s0, i1 = 1.0f / s1;
    #pragma unroll
    for (int q = 0; q < 32; q++) {
        r0[q * 32 + lane] *= i0;
        r1[q * 32 + lane] *= i1;
    }
}

// ---------------------------------------------------------------------------
// Kernel 0: split fp32 inputs into bf16 hi/lo planes
// covers: X (3x1048576), in_proj_w (589824), out_w (65536) = 3801088 elements
// ---------------------------------------------------------------------------
__global__ void __launch_bounds__(256) conv_kernel(
        const float* __restrict__ q, const float* __restrict__ k,
        const float* __restrict__ v, const float* __restrict__ W,
        const float* __restrict__ ow)
{
    int idx = blockIdx.x * 256 + threadIdx.x;
    float val;
    __nv_bfloat16 *ph, *pl;
    if (idx < 3145728) {
        int plane = idx >> 20, pos = idx & 1048575;
        const float* src = (plane == 0) ? q : ((plane == 1) ? k : v);
        val = src[pos];
        ph = &g_xh[plane][pos]; pl = &g_xl[plane][pos];
    } else if (idx < 3735552) {
        int pos = idx - 3145728;
        val = W[pos];
        ph = &g_wh[pos]; pl = &g_wl[pos];
    } else {
        int pos = idx - 3735552;
        val = ow[pos];
        ph = &g_owh[pos]; pl = &g_owl[pos];
    }
    __nv_bfloat16 hv = __float2bfloat16(val);
    *ph = hv;
    *pl = __float2bfloat16(val - __bfloat162float(hv));
}

// ---------------------------------------------------------------------------
// Kernel 1: packed in-projection via split-bf16 HMMA.
// C[4096 x 2304] = X_sel @ W^T + b (scaled), scattered to g_projh/l, g_v.
// grid (36, 64), warp w: m-block (w&3)*16, n-block (w>>2)*32.
// ---------------------------------------------------------------------------
__global__ void __launch_bounds__(256) proj_mma_kernel(const float* __restrict__ bias)
{
    int ct = blockIdx.x, rt = blockIdx.y;
    int j = ct >> 2;
    int xsel = (j == 2) ? 2 : ((j == 1 || j == 4 || j == 6 || j == 8) ? 1 : 0);
    int t = threadIdx.x, lane = t & 31, w = t >> 5;
    int wm = w & 3, wn = w >> 2;
    int n = lane >> 2, kq = (lane & 3) * 2;
    int m0 = rt * 64 + wm * 16;
    int n0 = ct * 64 + wn * 32;
    const __nv_bfloat16* Xh = g_xh[xsel];
    const __nv_bfloat16* Xl = g_xl[xsel];
    float d[4][4] = {};
    #pragma unroll 2
    for (int kt = 0; kt < 256; kt += 16) {
        int off = kt + kq;
        const __nv_bfloat16* xr0 = Xh + (m0 + n) * 256 + off;
        const __nv_bfloat16* xr1 = Xh + (m0 + n + 8) * 256 + off;
        const __nv_bfloat16* xl0 = Xl + (m0 + n) * 256 + off;
        const __nv_bfloat16* xl1 = Xl + (m0 + n + 8) * 256 + off;
        unsigned ah0 = ldu32(xr0),     ah1 = ldu32(xr1);
        unsigned ah2 = ldu32(xr0 + 8), ah3 = ldu32(xr1 + 8);
        unsigned al0 = ldu32(xl0),     al1 = ldu32(xl1);
        unsigned al2 = ldu32(xl0 + 8), al3 = ldu32(xl1 + 8);
        #pragma unroll
        for (int g = 0; g < 4; g++) {
            int nr = n0 + g * 8 + n;
            unsigned b0h = ldu32(g_wh + nr * 256 + off);
            unsigned b1h = ldu32(g_wh + nr * 256 + off + 8);
            unsigned b0l = ldu32(g_wl + nr * 256 + off);
            unsigned b1l = ldu32(g_wl + nr * 256 + off + 8);
            mma_bf16(d[g][0], d[g][1], d[g][2], d[g][3],
                     ah0, ah1, ah2, ah3, b0h, b1h);     // hi*hi
            mma_bf16(d[g][0], d[g][1], d[g][2], d[g][3],
                     al0, al1, al2, al3, b0h, b1h);     // lo*hi
            mma_bf16(d[g][0], d[g][1], d[g][2], d[g][3],
                     ah0, ah1, ah2, ah3, b0l, b1l);     // hi*lo
        }
    }
    float scale = (j == 0 || j == 7) ? SCALING : 1.0f;
    #pragma unroll
    for (int g = 0; g < 4; g++) {
        int cbase = n0 + g * 8 + kq;
        #pragma unroll
        for (int e = 0; e < 4; e++) {
            int r = m0 + n + (e >> 1) * 8;     // d0,d1 -> r; d2,d3 -> r+8
            int col = cbase + (e & 1);
            float val = (d[g][e] + bias[col]) * scale;
            int s = r >> 2, b = r & 3;
            int eo = col - j * 256;
            int bhp = b * 8 + (eo >> 5), dd = eo & 31;
            __nv_bfloat16 hv = __float2bfloat16(val);
            g_projh[j][bhp][s][dd] = hv;
            g_projl[j][bhp][s][dd] = __float2bfloat16(val - __bfloat162float(hv));
            if (j == 2) g_v[bhp][s][dd] = val;
        }
    }
}

// ---------------------------------------------------------------------------
// Kernel F1: per (bh, 8 rows): left/right logits (split-bf16 HMMA) ->
// softmax -> scans -> mask.  dyn smem: Ls[8192] Rs[8192] = 65536 B, 2 CTAs/SM
// (byte-identical to R7)
// ---------------------------------------------------------------------------
__global__ void __launch_bounds__(256, 2) f1_kernel()
{
    extern __shared__ float sm[];
    float* Ls = sm;
    float* Rs = sm + 8192;
    int t = threadIdx.x, lane = t & 31, w = t >> 5;
    int rt = blockIdx.x, bh = blockIdx.y;
    int row0 = rt * 8;
    int n = lane >> 2;
    int kq = (lane & 3) * 2;

    unsigned B[2][2][2][2];
    {
        const __nv_bfloat16* qh3 = &g_projh[3][bh][row0 + n][0];
        const __nv_bfloat16* ql3 = &g_projl[3][bh][row0 + n][0];
        const __nv_bfloat16* qh5 = &g_projh[5][bh][row0 + n][0];
        const __nv_bfloat16* ql5 = &g_projl[5][bh][row0 + n][0];
        B[0][0][0][0] = ldu32(qh3 + kq);      B[0][0][0][1] = ldu32(qh3 + kq + 8);
        B[0][0][1][0] = ldu32(qh3 + kq + 16); B[0][0][1][1] = ldu32(qh3 + kq + 24);
        B[0][1][0][0] = ldu32(ql3 + kq);      B[0][1][0][1] = ldu32(ql3 + kq + 8);
        B[0][1][1][0] = ldu32(ql3 + kq + 16); B[0][1][1][1] = ldu32(ql3 + kq + 24);
        B[1][0][0][0] = ldu32(qh5 + kq);      B[1][0][0][1] = ldu32(qh5 + kq + 8);
        B[1][0][1][0] = ldu32(qh5 + kq + 16); B[1][0][1][1] = ldu32(qh5 + kq + 24);
        B[1][1][0][0] = ldu32(ql5 + kq);      B[1][1][0][1] = ldu32(ql5 + kq + 8);
        B[1][1][1][0] = ldu32(ql5 + kq + 16); B[1][1][1][1] = ldu32(ql5 + kq + 24);
    }

    #pragma unroll 1
    for (int m = 0; m < 2; m++) {
        const __nv_bfloat16* Kh = &g_projh[m ? 6 : 4][bh][0][0];
        const __nv_bfloat16* Kl = &g_projl[m ? 6 : 4][bh][0][0];
        float* Obuf = m ? Rs : Ls;
        #pragma unroll 1
        for (int j = 0; j < 8; j++) {
            int col0 = (j * 8 + w) * 16;
            float d0 = 0.f, d1 = 0.f, d2 = 0.f, d3 = 0.f;
            #pragma unroll
            for (int ks = 0; ks < 2; ks++) {
                int off = ks * 16 + kq;
                const __nv_bfloat16* pa0 = Kh + (col0 + n) * 32 + off;
                const __nv_bfloat16* pa1 = Kh + (col0 + n + 8) * 32 + off;
                const __nv_bfloat16* pl0 = Kl + (col0 + n) * 32 + off;
                const __nv_bfloat16* pl1 = Kl + (col0 + n + 8) * 32 + off;
                unsigned ah0 = ldu32(pa0),     ah1 = ldu32(pa1);
                unsigned ah2 = ldu32(pa0 + 8), ah3 = ldu32(pa1 + 8);
                unsigned al0 = ldu32(pl0),     al1 = ldu32(pl1);
                unsigned al2 = ldu32(pl0 + 8), al3 = ldu32(pl1 + 8);
                mma_bf16(d0, d1, d2, d3, ah0, ah1, ah2, ah3,
                         B[m][0][ks][0], B[m][0][ks][1]);
                mma_bf16(d0, d1, d2, d3, al0, al1, al2, al3,
                         B[m][0][ks][0], B[m][0][ks][1]);
                mma_bf16(d0, d1, d2, d3, ah0, ah1, ah2, ah3,
                         B[m][1][ks][0], B[m][1][ks][1]);
            }
            int c = col0 + n;
            Obuf[kq * 1024 + c]           = d0;
            Obuf[(kq + 1) * 1024 + c]     = d1;
            Obuf[kq * 1024 + c + 8]       = d2;
            Obuf[(kq + 1) * 1024 + c + 8] = d3;
        }
    }
    __syncthreads();

    float* Lrow = Ls + w * 1024;
    float* Rrow = Rs + w * 1024;
    warp_softmax_row2(Lrow, Rrow, lane);

    float sL[32], sR[32];
    float runPL = 0.f, runPR = 0.f;
    #pragma unroll
    for (int q = 0; q < 32; q++) {
        float vL = Lrow[q * 32 + lane];
        float vR = Rrow[q * 32 + lane];
        float pL = vL, pR = vR;
        warp_iscan2(pL, pR, lane);
        float BL = __shfl_sync(0xffffffffu, pL, 31);
        float BR = __shfl_sync(0xffffffffu, pR, 31);
        runPL += pL;
        runPR += pR;
        Lrow[q * 32 + lane] = runPL;
        Rrow[q * 32 + lane] = runPR;
        sL[q] = BL - pL + vL;
        sR[q] = BR - pR + vR;
    }
    float* mout = &g_mask[bh][(size_t)(row0 + w) * 1024];
    float runSL = 0.f, runSR = 0.f;
    #pragma unroll
    for (int q = 31; q >= 0; q--) {
        runSL += sL[q];
        runSR += sR[q];
        mout[q * 32 + lane] = Lrow[q * 32 + lane] * runSR
                            + runSL * Rrow[q * 32 + lane];
    }
}

// ---------------------------------------------------------------------------
// Kernel F2: per (bh, 16 rows): global+local logits (HMMA) + mask combine ->
// softmax -> AV (SIMT fp32).  dyn smem: Cs[16384] Ps[4096] = 81920 B, 2 CTAs/SM
// epilogue now emits attn hi/lo bf16 planes for outproj_mma.
// ---------------------------------------------------------------------------
__global__ void __launch_bounds__(256, 2) f2_kernel()
{
    extern __shared__ float sm[];
    float* Cs = sm;
    float* Ps = sm + 16384;
    int t = threadIdx.x, lane = t & 31, w = t >> 5;
    int rt = blockIdx.x, bh = blockIdx.y;
    int row0 = rt * 16;
    int n = lane >> 2, kq = (lane & 3) * 2;

    unsigned B[2][2][2][2][2];
    #pragma unroll
    for (int mtx = 0; mtx < 2; mtx++) {
        int slice = mtx ? 7 : 0;
        #pragma unroll
        for (int rh = 0; rh < 2; rh++) {
            const __nv_bfloat16* qh = &g_projh[slice][bh][row0 + rh * 8 + n][0];
            const __nv_bfloat16* ql = &g_projl[slice][bh][row0 + rh * 8 + n][0];
            B[mtx][rh][0][0][0] = ldu32(qh + kq);      B[mtx][rh][0][0][1] = ldu32(qh + kq + 8);
            B[mtx][rh][0][1][0] = ldu32(qh + kq + 16); B[mtx][rh][0][1][1] = ldu32(qh + kq + 24);
            B[mtx][rh][1][0][0] = ldu32(ql + kq);      B[mtx][rh][1][0][1] = ldu32(ql + kq + 8);
            B[mtx][rh][1][1][0] = ldu32(ql + kq + 16); B[mtx][rh][1][1][1] = ldu32(ql + kq + 24);
        }
    }

    const __nv_bfloat16* K1h = &g_projh[1][bh][0][0];
    const __nv_bfloat16* K1l = &g_projl[1][bh][0][0];
    const __nv_bfloat16* K8h = &g_projh[8][bh][0][0];
    const __nv_bfloat16* K8l = &g_projl[8][bh][0][0];

    #pragma unroll 1
    for (int j = 0; j < 8; j++) {
        int col0 = (j * 8 + w) * 16;
        float g[8] = {}, lc[8] = {};
        #pragma unroll
        for (int ks = 0; ks < 2; ks++) {
            int off = ks * 16 + kq;
            const __nv_bfloat16* pa0 = K1h + (col0 + n) * 32 + off;
            const __nv_bfloat16* pa1 = K1h + (col0 + n + 8) * 32 + off;
            const __nv_bfloat16* pl0 = K1l + (col0 + n) * 32 + off;
            const __nv_bfloat16* pl1 = K1l + (col0 + n + 8) * 32 + off;
            unsigned ah0 = ldu32(pa0),     ah1 = ldu32(pa1);
            unsigned ah2 = ldu32(pa0 + 8), ah3 = ldu32(pa1 + 8);
            unsigned al0 = ldu32(pl0),     al1 = ldu32(pl1);
            unsigned al2 = ldu32(pl0 + 8), al3 = ldu32(pl1 + 8);
            #pragma unroll
            for (int rh = 0; rh < 2; rh++) {
                mma_bf16(g[rh*4+0], g[rh*4+1], g[rh*4+2], g[rh*4+3],
                         ah0, ah1, ah2, ah3, B[0][rh][0][ks][0], B[0][rh][0][ks][1]);
                mma_bf16(g[rh*4+0], g[rh*4+1], g[rh*4+2], g[rh*4+3],
                         al0, al1, al2, al3, B[0][rh][0][ks][0], B[0][rh][0][ks][1]);
                mma_bf16(g[rh*4+0], g[rh*4+1], g[rh*4+2], g[rh*4+3],
                         ah0, ah1, ah2, ah3, B[0][rh][1][ks][0], B[0][rh][1][ks][1]);
            }
        }
        #pragma unroll
        for (int ks = 0; ks < 2; ks++) {
            int off = ks * 16 + kq;
            const __nv_bfloat16* pa0 = K8h + (col0 + n) * 32 + off;
            const __nv_bfloat16* pa1 = K8h + (col0 + n + 8) * 32 + off;
            const __nv_bfloat16* pl0 = K8l + (col0 + n) * 32 + off;
            const __nv_bfloat16* pl1 = K8l + (col0 + n + 8) * 32 + off;
            unsigned ah0 = ldu32(pa0),     ah1 = ldu32(pa1);
            unsigned ah2 = ldu32(pa0 + 8), ah3 = ldu32(pa1 + 8);
            unsigned al0 = ldu32(pl0),     al1 = ldu32(pl1);
            unsigned al2 = ldu32(pl0 + 8), al3 = ldu32(pl1 + 8);
            #pragma unroll
            for (int rh = 0; rh < 2; rh++) {
                mma_bf16(lc[rh*4+0], lc[rh*4+1], lc[rh*4+2], lc[rh*4+3],
                         ah0, ah1, ah2, ah3, B[1][rh][0][ks][0], B[1][rh][0][ks][1]);
                mma_bf16(lc[rh*4+0], lc[rh*4+1], lc[rh*4+2], lc[rh*4+3],
                         al0, al1, al2, al3, B[1][rh][0][ks][0], B[1][rh][0][ks][1]);
                mma_bf16(lc[rh*4+0], lc[rh*4+1], lc[rh*4+2], lc[rh*4+3],
                         ah0, ah1, ah2, ah3, B[1][rh][1][ks][0], B[1][rh][1][ks][1]);
            }
        }
        int c = col0 + n;
        #pragma unroll
        for (int rh = 0; rh < 2; rh++) {
            int q = rh * 8 + kq;
            const float* mrow = &g_mask[bh][(size_t)(row0 + q) * 1024];
            float m0 = mrow[c], m1 = mrow[1024 + c];
            float m2 = mrow[c + 8], m3 = mrow[1024 + c + 8];
            Cs[q * 1024 + c]           = 0.1f * g[rh*4+0] + lc[rh*4+0] * m0;
            Cs[(q + 1) * 1024 + c]     = 0.1f * g[rh*4+1] + lc[rh*4+1] * m1;
            Cs[q * 1024 + c + 8]       = 0.1f * g[rh*4+2] + lc[rh*4+2] * m2;
            Cs[(q + 1) * 1024 + c + 8] = 0.1f * g[rh*4+3] + lc[rh*4+3] * m3;
        }
    }
    __syncthreads();

    warp_softmax_row2(Cs + w * 1024, Cs + (w + 8) * 1024, lane);
    __syncthreads();

    const float* Vsrc = &g_v[bh][0][0];
    int d = lane, jp = w;
    float acc[16];
    #pragma unroll
    for (int i = 0; i < 16; i++) acc[i] = 0.f;
    int base = jp * 128;
    #pragma unroll 2
    for (int jj = 0; jj < 128; jj += 4) {
        int j = base + jj;
        float v0 = Vsrc[(size_t)(j + 0) * 32 + d];
        float v1 = Vsrc[(size_t)(j + 1) * 32 + d];
        float v2 = Vsrc[(size_t)(j + 2) * 32 + d];
        float v3 = Vsrc[(size_t)(j + 3) * 32 + d];
        #pragma unroll
        for (int i = 0; i < 16; i++) {
            float4 c4 = *(const float4*)(Cs + i * 1024 + j);
            acc[i] += c4.x * v0 + c4.y * v1 + c4.z * v2 + c4.w * v3;
        }
    }
    #pragma unroll
    for (int i = 0; i < 16; i++) Ps[jp * 512 + i * 32 + d] = acc[i];
    __syncthreads();
    float s0 = 0.f, s1 = 0.f;
    #pragma unroll
    for (int p = 0; p < 8; p++) {
        s0 += Ps[p * 512 + w * 32 + lane];
        s1 += Ps[p * 512 + (w + 8) * 32 + lane];
    }
    int b = bh >> 3, hh = bh & 7;
    int r0i = ((row0 + w) * 4 + b) * 256 + hh * 32 + lane;
    int r1i = ((row0 + w + 8) * 4 + b) * 256 + hh * 32 + lane;
    __nv_bfloat16 h0 = __float2bfloat16(s0);
    __nv_bfloat16 h1 = __float2bfloat16(s1);
    g_attnh[r0i] = h0;
    g_attnl[r0i] = __float2bfloat16(s0 - __bfloat162float(h0));
    g_attnh[r1i] = h1;
    g_attnl[r1i] = __float2bfloat16(s1 - __bfloat162float(h1));
}

// ---------------------------------------------------------------------------
// Kernel 4: out-projection via split-bf16 HMMA.
// out[4096 x 256] = attn @ out_w^T + out_b.  grid (4, 64).
// ---------------------------------------------------------------------------
__global__ void __launch_bounds__(256) outproj_mma_kernel(
        const float* __restrict__ bias, float* __restrict__ out)
{
    int ct = blockIdx.x, rt = blockIdx.y;
    int t = threadIdx.x, lane = t & 31, w = t >> 5;
    int wm = w & 3, wn = w >> 2;
    int n = lane >> 2, kq = (lane & 3) * 2;
    int m0 = rt * 64 + wm * 16;
    int n0 = ct * 64 + wn * 32;
    float d[4][4] = {};
    #pragma unroll 2
    for (int kt = 0; kt < 256; kt += 16) {
        int off = kt + kq;
        const __nv_bfloat16* xr0 = g_attnh + (m0 + n) * 256 + off;
        const __nv_bfloat16* xr1 = g_attnh + (m0 + n + 8) * 256 + off;
        const __nv_bfloat16* xl0 = g_attnl + (m0 + n) * 256 + off;
        const __nv_bfloat16* xl1 = g_attnl + (m0 + n + 8) * 256 + off;
        unsigned ah0 = ldu32(xr0),     ah1 = ldu32(xr1);
        unsigned ah2 = ldu32(xr0 + 8), ah3 = ldu32(xr1 + 8);
        unsigned al0 = ldu32(xl0),     al1 = ldu32(xl1);
        unsigned al2 = ldu32(xl0 + 8), al3 = ldu32(xl1 + 8);
        #pragma unroll
        for (int g = 0; g < 4; g++) {
            int nr = n0 + g * 8 + n;
            unsigned b0h = ldu32(g_owh + nr * 256 + off);
            unsigned b1h = ldu32(g_owh + nr * 256 + off + 8);
            unsigned b0l = ldu32(g_owl + nr * 256 + off);
            unsigned b1l = ldu32(g_owl + nr * 256 + off + 8);
            mma_bf16(d[g][0], d[g][1], d[g][2], d[g][3],
                     ah0, ah1, ah2, ah3, b0h, b1h);
            mma_bf16(d[g][0], d[g][1], d[g][2], d[g][3],
                     al0, al1, al2, al3, b0h, b1h);
            mma_bf16(d[g][0], d[g][1], d[g][2], d[g][3],
                     ah0, ah1, ah2, ah3, b0l, b1l);
        }
    }
    #pragma unroll
    for (int g = 0; g < 4; g++) {
        int cbase = n0 + g * 8 + kq;
        #pragma unroll
        for (int e = 0; e < 4; e++) {
            int r = m0 + n + (e >> 1) * 8;
            int col = cbase + (e & 1);
            out[r * 256 + col] = d[g][e] + bias[col];
        }
    }
}

// ---------------------------------------------------------------------------
// Kernel 5: consistent_mask = sum over bh of g_mask (float4 vectorized)
// ---------------------------------------------------------------------------
__global__ void __launch_bounds__(256) mask_reduce_kernel(float* __restrict__ out)
{
    int i4 = (blockIdx.x * 256 + threadIdx.x) * 4;
    float4 s = {0.f, 0.f, 0.f, 0.f};
    #pragma unroll
    for (int bh = 0; bh < 32; bh++) {
        float4 v = *(const float4*)&g_mask[bh][i4];
        s.x += v.x; s.y += v.y; s.z += v.z; s.w += v.w;
    }
    *(float4*)(out + i4) = s;
}

// ---------------------------------------------------------------------------
extern "C" void kernel_launch(void* const* d_in, const int* in_sizes, int n_in,
                              void* d_out, int out_size)
{
    const float* q   = (const float*)d_in[0];
    const float* k   = (const float*)d_in[1];
    const float* v   = (const float*)d_in[2];
    const float* ipw = (const float*)d_in[3];
    const float* ipb = (const float*)d_in[4];
    const float* ow  = (const float*)d_in[5];
    const float* ob  = (const float*)d_in[6];
    float* out = (float*)d_out;

    cudaFuncSetAttribute(f1_kernel, cudaFuncAttributeMaxDynamicSharedMemorySize, 65536);
    cudaFuncSetAttribute(f2_kernel, cudaFuncAttributeMaxDynamicSharedMemorySize, 81920);

    conv_kernel<<<14848, 256>>>(q, k, v, ipw, ow);
    proj_mma_kernel<<<dim3(36, 64), 256>>>(ipb);
    f1_kernel<<<dim3(128, 32), 256, 65536>>>();
    f2_kernel<<<dim3(64, 32), 256, 81920>>>();
    outproj_mma_kernel<<<dim3(4, 64), 256>>>(ob, out);
    mask_reduce_kernel<<<1024, 256>>>(out + 1048576);
}

// round 9
// speedup vs baseline: 1.0397x; 1.0397x over previous
#include <cuda_runtime.h>
#include <cuda_bf16.h>

#define SCALING 0.17677669529663687f

// ---------------------------------------------------------------------------
// Scratch (static device globals — allowed; no runtime allocation)
// ---------------------------------------------------------------------------
__device__ __nv_bfloat16 g_projh[9][32][1024][32];  // bf16 hi planes
__device__ __nv_bfloat16 g_projl[9][32][1024][32];  // bf16 lo planes
__device__ float g_v[32][1024][32];                 // V fp32 (AV)
__device__ float g_mask[32][1024 * 1024];           // local_mask
__device__ float g_attn_pre[4096 * 256];            // pre-out-proj fp32

// ---------------------------------------------------------------------------
// mma.sync m16n8k16 bf16 (HMMA), D/C fp32
// ---------------------------------------------------------------------------
__device__ __forceinline__ void mma_bf16(
    float& d0, float& d1, float& d2, float& d3,
    unsigned a0, unsigned a1, unsigned a2, unsigned a3,
    unsigned b0, unsigned b1)
{
    asm volatile(
        "mma.sync.aligned.m16n8k16.row.col.f32.bf16.bf16.f32 "
        "{%0,%1,%2,%3}, {%4,%5,%6,%7}, {%8,%9}, {%0,%1,%2,%3};\n"
        : "+f"(d0), "+f"(d1), "+f"(d2), "+f"(d3)
        : "r"(a0), "r"(a1), "r"(a2), "r"(a3), "r"(b0), "r"(b1));
}
__device__ __forceinline__ unsigned ldu32(const __nv_bfloat16* p) {
    return *(const unsigned*)p;
}
__device__ __forceinline__ unsigned s2u(const void* p) {
    unsigned a;
    asm("{ .reg .u64 t; cvta.to.shared.u64 t, %1; cvt.u32.u64 %0, t; }"
        : "=r"(a) : "l"(p));
    return a;
}
__device__ __forceinline__ void ldsm_x4(unsigned r[4], unsigned addr) {
    asm volatile("ldmatrix.sync.aligned.m8n8.x4.shared.b16 {%0,%1,%2,%3}, [%4];"
        : "=r"(r[0]), "=r"(r[1]), "=r"(r[2]), "=r"(r[3]) : "r"(addr));
}

// ---------------------------------------------------------------------------
// Stage a 128-col K chunk (128 rows x 32 bf16 = 64B/row) into SMEM with rows
// padded to 80B (LDSM bank-conflict-free: (r*20)%32 distinct over 8 rows).
// Fully coalesced LDG.128 / STS.128.
// ---------------------------------------------------------------------------
__device__ __forceinline__ void stage_chunk(char* __restrict__ dst,
                                            const __nv_bfloat16* __restrict__ src,
                                            int t)
{
    #pragma unroll
    for (int it = 0; it < 2; it++) {
        int u = t + it * 256;
        int r = u >> 2, c = u & 3;
        *(float4*)(dst + r * 80 + c * 16) =
            *(const float4*)((const char*)src + r * 64 + c * 16);
    }
}

// ---------------------------------------------------------------------------
// warp helpers (R6-proven)
// ---------------------------------------------------------------------------
__device__ __forceinline__ void warp_iscan2(float& a, float& b, int lane) {
    #pragma unroll
    for (int o = 1; o < 32; o <<= 1) {
        float ua = __shfl_up_sync(0xffffffffu, a, o);
        float ub = __shfl_up_sync(0xffffffffu, b, o);
        if (lane >= o) { a += ua; b += ub; }
    }
}
__device__ __forceinline__ void warp_softmax_row2(float* r0, float* r1, int lane) {
    float m0 = -1e30f, m1 = -1e30f;
    #pragma unroll
    for (int q = 0; q < 32; q++) {
        m0 = fmaxf(m0, r0[q * 32 + lane]);
        m1 = fmaxf(m1, r1[q * 32 + lane]);
    }
    #pragma unroll
    for (int o = 16; o; o >>= 1) {
        m0 = fmaxf(m0, __shfl_xor_sync(0xffffffffu, m0, o));
        m1 = fmaxf(m1, __shfl_xor_sync(0xffffffffu, m1, o));
    }
    float s0 = 0.f, s1 = 0.f;
    #pragma unroll
    for (int q = 0; q < 32; q++) {
        float e0 = __expf(r0[q * 32 + lane] - m0);
        float e1 = __expf(r1[q * 32 + lane] - m1);
        r0[q * 32 + lane] = e0;
        r1[q * 32 + lane] = e1;
        s0 += e0; s1 += e1;
    }
    #pragma unroll
    for (int o = 16; o; o >>= 1) {
        s0 += __shfl_xor_sync(0xffffffffu, s0, o);
        s1 += __shfl_xor_sync(0xffffffffu, s1, o);
    }
    float i0 = 1.0f / s0, i1 = 1.0f / s1;
    #pragma unroll
    for (int q = 0; q < 32; q++) {
        r0[q * 32 + lane] *= i0;
        r1[q * 32 + lane] *= i1;
    }
}

// ---------------------------------------------------------------------------
// Kernel 1: packed in-projection (scalar FFMA, R7-proven) + split-bf16 planes
// ---------------------------------------------------------------------------
__global__ void __launch_bounds__(256) proj_kernel(
        const float* __restrict__ xq, const float* __restrict__ xk,
        const float* __restrict__ xv, const float* __restrict__ W,
        const float* __restrict__ bias)
{
    __shared__ float As[16][68];
    __shared__ float Bs[16][68];
    int ct = blockIdx.x, rt = blockIdx.y;
    int j = ct >> 2;
    const float* X = (j == 2) ? xv
                   : ((j == 1 || j == 4 || j == 6 || j == 8) ? xk : xq);
    int t = threadIdx.x;
    int tx = t & 15, ty = t >> 4;
    int row0 = rt * 64, col0 = ct * 64;
    float acc[4][4] = {};
    for (int kt = 0; kt < 256; kt += 16) {
        #pragma unroll
        for (int l = 0; l < 4; l++) {
            int u = t + l * 256;
            int kk = u & 15, m = u >> 4;
            As[kk][m] = X[(row0 + m) * 256 + kt + kk];
            Bs[kk][m] = W[(col0 + m) * 256 + kt + kk];
        }
        __syncthreads();
        #pragma unroll
        for (int kk = 0; kk < 16; kk++) {
            float4 av = *(const float4*)(&As[kk][ty * 4]);
            float4 bv = *(const float4*)(&Bs[kk][tx * 4]);
            float a[4] = {av.x, av.y, av.z, av.w};
            float b[4] = {bv.x, bv.y, bv.z, bv.w};
            #pragma unroll
            for (int i = 0; i < 4; i++)
                #pragma unroll
                for (int c = 0; c < 4; c++)
                    acc[i][c] += a[i] * b[c];
        }
        __syncthreads();
    }
    float scale = (j == 0 || j == 7) ? SCALING : 1.0f;
    #pragma unroll
    for (int i = 0; i < 4; i++) {
        int row = row0 + ty * 4 + i;
        int s = row >> 2, b = row & 3;
        #pragma unroll
        for (int c = 0; c < 4; c++) {
            int col = col0 + tx * 4 + c;
            int eo = col - j * 256;
            float val = (acc[i][c] + bias[col]) * scale;
            int bhp = b * 8 + (eo >> 5), dd = eo & 31;
            __nv_bfloat16 h = __float2bfloat16(val);
            g_projh[j][bhp][s][dd] = h;
            g_projl[j][bhp][s][dd] = __float2bfloat16(val - __bfloat162float(h));
            if (j == 2) g_v[bhp][s][dd] = val;
        }
    }
}

// ---------------------------------------------------------------------------
// Kernel F1: per (bh, 8 rows): left/right logits (LDSM + split-bf16 HMMA) ->
// softmax -> scans -> mask.
// dyn smem: Ls 32768 + Rs 32768 + SKh 10240 + SKl 10240 = 86016 B, 2 CTAs/SM
// ---------------------------------------------------------------------------
__global__ void __launch_bounds__(256, 2) f1_kernel()
{
    extern __shared__ float sm[];
    float* Ls = sm;                       // 8192 floats
    float* Rs = sm + 8192;                // 8192 floats
    char*  SKh = (char*)(sm + 16384);     // 10240 B
    char*  SKl = SKh + 10240;             // 10240 B
    int t = threadIdx.x, lane = t & 31, w = t >> 5;
    int rt = blockIdx.x, bh = blockIdx.y;
    int row0 = rt * 8;
    int n = lane >> 2, kq = (lane & 3) * 2;

    // B-frags (Q rows), register preload: [mtx][hi/lo][kstep][reg]
    unsigned B[2][2][2][2];
    {
        const __nv_bfloat16* qh3 = &g_projh[3][bh][row0 + n][0];
        const __nv_bfloat16* ql3 = &g_projl[3][bh][row0 + n][0];
        const __nv_bfloat16* qh5 = &g_projh[5][bh][row0 + n][0];
        const __nv_bfloat16* ql5 = &g_projl[5][bh][row0 + n][0];
        B[0][0][0][0] = ldu32(qh3 + kq);      B[0][0][0][1] = ldu32(qh3 + kq + 8);
        B[0][0][1][0] = ldu32(qh3 + kq + 16); B[0][0][1][1] = ldu32(qh3 + kq + 24);
        B[0][1][0][0] = ldu32(ql3 + kq);      B[0][1][0][1] = ldu32(ql3 + kq + 8);
        B[0][1][1][0] = ldu32(ql3 + kq + 16); B[0][1][1][1] = ldu32(ql3 + kq + 24);
        B[1][0][0][0] = ldu32(qh5 + kq);      B[1][0][0][1] = ldu32(qh5 + kq + 8);
        B[1][0][1][0] = ldu32(qh5 + kq + 16); B[1][0][1][1] = ldu32(qh5 + kq + 24);
        B[1][1][0][0] = ldu32(ql5 + kq);      B[1][1][0][1] = ldu32(ql5 + kq + 8);
        B[1][1][1][0] = ldu32(ql5 + kq + 16); B[1][1][1][1] = ldu32(ql5 + kq + 24);
    }

    unsigned skh = s2u(SKh), skl = s2u(SKl);
    unsigned fragoff = (unsigned)(w * 16 * 80) + (lane & 15) * 80 + (lane >> 4) * 16;

    #pragma unroll 1
    for (int m = 0; m < 2; m++) {
        const __nv_bfloat16* Kh = &g_projh[m ? 6 : 4][bh][0][0];
        const __nv_bfloat16* Kl = &g_projl[m ? 6 : 4][bh][0][0];
        float* Obuf = m ? Rs : Ls;
        #pragma unroll 1
        for (int ch = 0; ch < 8; ch++) {
            __syncthreads();
            stage_chunk(SKh, Kh + ch * 128 * 32, t);
            stage_chunk(SKl, Kl + ch * 128 * 32, t);
            __syncthreads();
            unsigned ah[2][4], al[2][4];
            ldsm_x4(ah[0], skh + fragoff);
            ldsm_x4(ah[1], skh + fragoff + 32);
            ldsm_x4(al[0], skl + fragoff);
            ldsm_x4(al[1], skl + fragoff + 32);
            float d0 = 0.f, d1 = 0.f, d2 = 0.f, d3 = 0.f;
            #pragma unroll
            for (int ks = 0; ks < 2; ks++) {
                mma_bf16(d0, d1, d2, d3, ah[ks][0], ah[ks][1], ah[ks][2], ah[ks][3],
                         B[m][0][ks][0], B[m][0][ks][1]);   // hi*hi
                mma_bf16(d0, d1, d2, d3, al[ks][0], al[ks][1], al[ks][2], al[ks][3],
                         B[m][0][ks][0], B[m][0][ks][1]);   // lo*hi
                mma_bf16(d0, d1, d2, d3, ah[ks][0], ah[ks][1], ah[ks][2], ah[ks][3],
                         B[m][1][ks][0], B[m][1][ks][1]);   // hi*lo
            }
            int c = ch * 128 + w * 16 + n;
            Obuf[kq * 1024 + c]           = d0;
            Obuf[(kq + 1) * 1024 + c]     = d1;
            Obuf[kq * 1024 + c + 8]       = d2;
            Obuf[(kq + 1) * 1024 + c + 8] = d3;
        }
    }
    __syncthreads();

    // ---- softmax + 2-level prefix/suffix -> mask (R6-proven) --------------
    float* Lrow = Ls + w * 1024;
    float* Rrow = Rs + w * 1024;
    warp_softmax_row2(Lrow, Rrow, lane);

    float sL[32], sR[32];
    float runPL = 0.f, runPR = 0.f;
    #pragma unroll
    for (int q = 0; q < 32; q++) {
        float vL = Lrow[q * 32 + lane];
        float vR = Rrow[q * 32 + lane];
        float pL = vL, pR = vR;
        warp_iscan2(pL, pR, lane);
        float BL = __shfl_sync(0xffffffffu, pL, 31);
        float BR = __shfl_sync(0xffffffffu, pR, 31);
        runPL += pL;
        runPR += pR;
        Lrow[q * 32 + lane] = runPL;
        Rrow[q * 32 + lane] = runPR;
        sL[q] = BL - pL + vL;
        sR[q] = BR - pR + vR;
    }
    float* mout = &g_mask[bh][(size_t)(row0 + w) * 1024];
    float runSL = 0.f, runSR = 0.f;
    #pragma unroll
    for (int q = 31; q >= 0; q--) {
        runSL += sL[q];
        runSR += sR[q];
        mout[q * 32 + lane] = Lrow[q * 32 + lane] * runSR
                            + runSL * Rrow[q * 32 + lane];
    }
}

// ---------------------------------------------------------------------------
// Kernel F2: per (bh, 16 rows): global+local logits (LDSM HMMA) + mask
// combine -> softmax -> AV (SIMT fp32).
// dyn smem: Cs 65536 + SKh 10240 + SKl 10240 = 86016 B, 2 CTAs/SM
// ---------------------------------------------------------------------------
__global__ void __launch_bounds__(256, 2) f2_kernel()
{
    extern __shared__ float sm[];
    float* Cs = sm;                       // 16384 floats
    char*  SKh = (char*)(sm + 16384);     // 10240 B
    char*  SKl = SKh + 10240;             // 10240 B
    float* Ps = (float*)SKh;              // AV partials overlay (16384 <= 20480)
    int t = threadIdx.x, lane = t & 31, w = t >> 5;
    int rt = blockIdx.x, bh = blockIdx.y;
    int row0 = rt * 16;
    int n = lane >> 2, kq = (lane & 3) * 2;

    // B-frags: [mtx][rowhalf][hi/lo][kstep][reg]
    unsigned B[2][2][2][2][2];
    #pragma unroll
    for (int mtx = 0; mtx < 2; mtx++) {
        int slice = mtx ? 7 : 0;
        #pragma unroll
        for (int rh = 0; rh < 2; rh++) {
            const __nv_bfloat16* qh = &g_projh[slice][bh][row0 + rh * 8 + n][0];
            const __nv_bfloat16* ql = &g_projl[slice][bh][row0 + rh * 8 + n][0];
            B[mtx][rh][0][0][0] = ldu32(qh + kq);      B[mtx][rh][0][0][1] = ldu32(qh + kq + 8);
            B[mtx][rh][0][1][0] = ldu32(qh + kq + 16); B[mtx][rh][0][1][1] = ldu32(qh + kq + 24);
            B[mtx][rh][1][0][0] = ldu32(ql + kq);      B[mtx][rh][1][0][1] = ldu32(ql + kq + 8);
            B[mtx][rh][1][1][0] = ldu32(ql + kq + 16); B[mtx][rh][1][1][1] = ldu32(ql + kq + 24);
        }
    }

    unsigned skh = s2u(SKh), skl = s2u(SKl);
    unsigned fragoff = (unsigned)(w * 16 * 80) + (lane & 15) * 80 + (lane >> 4) * 16;

    const __nv_bfloat16* K1h = &g_projh[1][bh][0][0];
    const __nv_bfloat16* K1l = &g_projl[1][bh][0][0];
    const __nv_bfloat16* K8h = &g_projh[8][bh][0][0];
    const __nv_bfloat16* K8l = &g_projl[8][bh][0][0];

    #pragma unroll 1
    for (int ch = 0; ch < 8; ch++) {
        float g[8] = {}, lc[8] = {};
        // ---- global logits: K1 chunk ----
        __syncthreads();
        stage_chunk(SKh, K1h + ch * 128 * 32, t);
        stage_chunk(SKl, K1l + ch * 128 * 32, t);
        __syncthreads();
        {
            unsigned ah[2][4], al[2][4];
            ldsm_x4(ah[0], skh + fragoff);
            ldsm_x4(ah[1], skh + fragoff + 32);
            ldsm_x4(al[0], skl + fragoff);
            ldsm_x4(al[1], skl + fragoff + 32);
            #pragma unroll
            for (int ks = 0; ks < 2; ks++)
                #pragma unroll
                for (int rh = 0; rh < 2; rh++) {
                    mma_bf16(g[rh*4+0], g[rh*4+1], g[rh*4+2], g[rh*4+3],
                             ah[ks][0], ah[ks][1], ah[ks][2], ah[ks][3],
                             B[0][rh][0][ks][0], B[0][rh][0][ks][1]);
                    mma_bf16(g[rh*4+0], g[rh*4+1], g[rh*4+2], g[rh*4+3],
                             al[ks][0], al[ks][1], al[ks][2], al[ks][3],
                             B[0][rh][0][ks][0], B[0][rh][0][ks][1]);
                    mma_bf16(g[rh*4+0], g[rh*4+1], g[rh*4+2], g[rh*4+3],
                             ah[ks][0], ah[ks][1], ah[ks][2], ah[ks][3],
                             B[0][rh][1][ks][0], B[0][rh][1][ks][1]);
                }
        }
        // ---- local logits: K8 chunk ----
        __syncthreads();
        stage_chunk(SKh, K8h + ch * 128 * 32, t);
        stage_chunk(SKl, K8l + ch * 128 * 32, t);
        __syncthreads();
        {
            unsigned ah[2][4], al[2][4];
            ldsm_x4(ah[0], skh + fragoff);
            ldsm_x4(ah[1], skh + fragoff + 32);
            ldsm_x4(al[0], skl + fragoff);
            ldsm_x4(al[1], skl + fragoff + 32);
            #pragma unroll
            for (int ks = 0; ks < 2; ks++)
                #pragma unroll
                for (int rh = 0; rh < 2; rh++) {
                    mma_bf16(lc[rh*4+0], lc[rh*4+1], lc[rh*4+2], lc[rh*4+3],
                             ah[ks][0], ah[ks][1], ah[ks][2], ah[ks][3],
                             B[1][rh][0][ks][0], B[1][rh][0][ks][1]);
                    mma_bf16(lc[rh*4+0], lc[rh*4+1], lc[rh*4+2], lc[rh*4+3],
                             al[ks][0], al[ks][1], al[ks][2], al[ks][3],
                             B[1][rh][0][ks][0], B[1][rh][0][ks][1]);
                    mma_bf16(lc[rh*4+0], lc[rh*4+1], lc[rh*4+2], lc[rh*4+3],
                             ah[ks][0], ah[ks][1], ah[ks][2], ah[ks][3],
                             B[1][rh][1][ks][0], B[1][rh][1][ks][1]);
                }
        }
        // ---- combine with mask and store ----
        int c = ch * 128 + w * 16 + n;
        #pragma unroll
        for (int rh = 0; rh < 2; rh++) {
            int q = rh * 8 + kq;
            const float* mrow = &g_mask[bh][(size_t)(row0 + q) * 1024];
            float m0 = mrow[c], m1 = mrow[1024 + c];
            float m2 = mrow[c + 8], m3 = mrow[1024 + c + 8];
            Cs[q * 1024 + c]           = 0.1f * g[rh*4+0] + lc[rh*4+0] * m0;
            Cs[(q + 1) * 1024 + c]     = 0.1f * g[rh*4+1] + lc[rh*4+1] * m1;
            Cs[q * 1024 + c + 8]       = 0.1f * g[rh*4+2] + lc[rh*4+2] * m2;
            Cs[(q + 1) * 1024 + c + 8] = 0.1f * g[rh*4+3] + lc[rh*4+3] * m3;
        }
    }
    __syncthreads();

    warp_softmax_row2(Cs + w * 1024, Cs + (w + 8) * 1024, lane);
    __syncthreads();

    // ---- AV: thread (d=lane, jp=w) owns j-slice [128w, 128w+128) ----------
    const float* Vsrc = &g_v[bh][0][0];
    int d = lane, jp = w;
    float acc[16];
    #pragma unroll
    for (int i = 0; i < 16; i++) acc[i] = 0.f;
    int base = jp * 128;
    #pragma unroll 2
    for (int jj = 0; jj < 128; jj += 4) {
        int j = base + jj;
        float v0 = Vsrc[(size_t)(j + 0) * 32 + d];
        float v1 = Vsrc[(size_t)(j + 1) * 32 + d];
        float v2 = Vsrc[(size_t)(j + 2) * 32 + d];
        float v3 = Vsrc[(size_t)(j + 3) * 32 + d];
        #pragma unroll
        for (int i = 0; i < 16; i++) {
            float4 c4 = *(const float4*)(Cs + i * 1024 + j);
            acc[i] += c4.x * v0 + c4.y * v1 + c4.z * v2 + c4.w * v3;
        }
    }
    #pragma unroll
    for (int i = 0; i < 16; i++) Ps[jp * 512 + i * 32 + d] = acc[i];
    __syncthreads();
    float s0 = 0.f, s1 = 0.f;
    #pragma unroll
    for (int p = 0; p < 8; p++) {
        s0 += Ps[p * 512 + w * 32 + lane];
        s1 += Ps[p * 512 + (w + 8) * 32 + lane];
    }
    int b = bh >> 3, hh = bh & 7;
    g_attn_pre[((row0 + w) * 4 + b) * 256 + hh * 32 + lane] = s0;
    g_attn_pre[((row0 + w + 8) * 4 + b) * 256 + hh * 32 + lane] = s1;
}

// ---------------------------------------------------------------------------
// Kernel 4: out-projection (scalar FFMA, R7-proven)
// ---------------------------------------------------------------------------
__global__ void __launch_bounds__(256) outproj_kernel(
        const float* __restrict__ W, const float* __restrict__ bias,
        float* __restrict__ out)
{
    __shared__ float As[16][68];
    __shared__ float Bs[16][68];
    int ct = blockIdx.x, rt = blockIdx.y;
    int t = threadIdx.x;
    int tx = t & 15, ty = t >> 4;
    int row0 = rt * 64, col0 = ct * 64;
    float acc[4][4] = {};
    for (int kt = 0; kt < 256; kt += 16) {
        #pragma unroll
        for (int l = 0; l < 4; l++) {
            int u = t + l * 256;
            int kk = u & 15, m = u >> 4;
            As[kk][m] = g_attn_pre[(row0 + m) * 256 + kt + kk];
            Bs[kk][m] = W[(col0 + m) * 256 + kt + kk];
        }
        __syncthreads();
        #pragma unroll
        for (int kk = 0; kk < 16; kk++) {
            float4 av = *(const float4*)(&As[kk][ty * 4]);
            float4 bv = *(const float4*)(&Bs[kk][tx * 4]);
            float a[4] = {av.x, av.y, av.z, av.w};
            float b[4] = {bv.x, bv.y, bv.z, bv.w};
            #pragma unroll
            for (int i = 0; i < 4; i++)
                #pragma unroll
                for (int c = 0; c < 4; c++)
                    acc[i][c] += a[i] * b[c];
        }
        __syncthreads();
    }
    #pragma unroll
    for (int i = 0; i < 4; i++) {
        int row = row0 + ty * 4 + i;
        #pragma unroll
        for (int c = 0; c < 4; c++) {
            int col = col0 + tx * 4 + c;
            out[row * 256 + col] = acc[i][c] + bias[col];
        }
    }
}

// ---------------------------------------------------------------------------
// Kernel 5: consistent_mask = sum over bh of g_mask (float4 vectorized)
// ---------------------------------------------------------------------------
__global__ void __launch_bounds__(256) mask_reduce_kernel(float* __restrict__ out)
{
    int i4 = (blockIdx.x * 256 + threadIdx.x) * 4;
    float4 s = {0.f, 0.f, 0.f, 0.f};
    #pragma unroll
    for (int bh = 0; bh < 32; bh++) {
        float4 v = *(const float4*)&g_mask[bh][i4];
        s.x += v.x; s.y += v.y; s.z += v.z; s.w += v.w;
    }
    *(float4*)(out + i4) = s;
}

// ---------------------------------------------------------------------------
extern "C" void kernel_launch(void* const* d_in, const int* in_sizes, int n_in,
                              void* d_out, int out_size)
{
    const float* q   = (const float*)d_in[0];
    const float* k   = (const float*)d_in[1];
    const float* v   = (const float*)d_in[2];
    const float* ipw = (const float*)d_in[3];
    const float* ipb = (const float*)d_in[4];
    const float* ow  = (const float*)d_in[5];
    const float* ob  = (const float*)d_in[6];
    float* out = (float*)d_out;

    cudaFuncSetAttribute(f1_kernel, cudaFuncAttributeMaxDynamicSharedMemorySize, 86016);
    cudaFuncSetAttribute(f2_kernel, cudaFuncAttributeMaxDynamicSharedMemorySize, 86016);

    proj_kernel<<<dim3(36, 64), 256>>>(q, k, v, ipw, ipb);
    f1_kernel<<<dim3(128, 32), 256, 86016>>>();
    f2_kernel<<<dim3(64, 32), 256, 86016>>>();
    outproj_kernel<<<dim3(4, 64), 256>>>(ow, ob, out);
    mask_reduce_kernel<<<1024, 256>>>(out + 1048576);
}

// round 10
// speedup vs baseline: 1.2903x; 1.2410x over previous
#include <cuda_runtime.h>
#include <cuda_bf16.h>

#define SCALING 0.17677669529663687f

// ---------------------------------------------------------------------------
// Scratch (static device globals — allowed; no runtime allocation)
// ---------------------------------------------------------------------------
__device__ __nv_bfloat16 g_projh[9][32][1024][32];  // bf16 hi planes
__device__ __nv_bfloat16 g_projl[9][32][1024][32];  // bf16 lo planes
__device__ float g_v[32][1024][32];                 // V fp32 (AV)
__device__ float g_mask[32][1024 * 1024];           // local_mask
__device__ float g_attn_pre[4096 * 256];            // pre-out-proj fp32

// ---------------------------------------------------------------------------
// mma.sync m16n8k16 bf16 (HMMA), D/C fp32
// ---------------------------------------------------------------------------
__device__ __forceinline__ void mma_bf16(
    float& d0, float& d1, float& d2, float& d3,
    unsigned a0, unsigned a1, unsigned a2, unsigned a3,
    unsigned b0, unsigned b1)
{
    asm volatile(
        "mma.sync.aligned.m16n8k16.row.col.f32.bf16.bf16.f32 "
        "{%0,%1,%2,%3}, {%4,%5,%6,%7}, {%8,%9}, {%0,%1,%2,%3};\n"
        : "+f"(d0), "+f"(d1), "+f"(d2), "+f"(d3)
        : "r"(a0), "r"(a1), "r"(a2), "r"(a3), "r"(b0), "r"(b1));
}
__device__ __forceinline__ unsigned ldu32(const __nv_bfloat16* p) {
    return *(const unsigned*)p;
}
__device__ __forceinline__ unsigned s2u(const void* p) {
    unsigned a;
    asm("{ .reg .u64 t; cvta.to.shared.u64 t, %1; cvt.u32.u64 %0, t; }"
        : "=r"(a) : "l"(p));
    return a;
}
__device__ __forceinline__ void ldsm_x4(unsigned r[4], unsigned addr) {
    asm volatile("ldmatrix.sync.aligned.m8n8.x4.shared.b16 {%0,%1,%2,%3}, [%4];"
        : "=r"(r[0]), "=r"(r[1]), "=r"(r[2]), "=r"(r[3]) : "r"(addr));
}

// ---------------------------------------------------------------------------
// warp helpers (R6-proven)
// ---------------------------------------------------------------------------
__device__ __forceinline__ void warp_iscan2(float& a, float& b, int lane) {
    #pragma unroll
    for (int o = 1; o < 32; o <<= 1) {
        float ua = __shfl_up_sync(0xffffffffu, a, o);
        float ub = __shfl_up_sync(0xffffffffu, b, o);
        if (lane >= o) { a += ua; b += ub; }
    }
}
__device__ __forceinline__ void warp_softmax_row2(float* r0, float* r1, int lane) {
    float m0 = -1e30f, m1 = -1e30f;
    #pragma unroll
    for (int q = 0; q < 32; q++) {
        m0 = fmaxf(m0, r0[q * 32 + lane]);
        m1 = fmaxf(m1, r1[q * 32 + lane]);
    }
    #pragma unroll
    for (int o = 16; o; o >>= 1) {
        m0 = fmaxf(m0, __shfl_xor_sync(0xffffffffu, m0, o));
        m1 = fmaxf(m1, __shfl_xor_sync(0xffffffffu, m1, o));
    }
    float s0 = 0.f, s1 = 0.f;
    #pragma unroll
    for (int q = 0; q < 32; q++) {
        float e0 = __expf(r0[q * 32 + lane] - m0);
        float e1 = __expf(r1[q * 32 + lane] - m1);
        r0[q * 32 + lane] = e0;
        r1[q * 32 + lane] = e1;
        s0 += e0; s1 += e1;
    }
    #pragma unroll
    for (int o = 16; o; o >>= 1) {
        s0 += __shfl_xor_sync(0xffffffffu, s0, o);
        s1 += __shfl_xor_sync(0xffffffffu, s1, o);
    }
    float i0 = 1.0f / s0, i1 = 1.0f / s1;
    #pragma unroll
    for (int q = 0; q < 32; q++) {
        r0[q * 32 + lane] *= i0;
        r1[q * 32 + lane] *= i1;
    }
}

// ---------------------------------------------------------------------------
// convert helper: float4 -> 4 hi bf16 + 4 lo bf16, stored as two bf162 each
// ---------------------------------------------------------------------------
__device__ __forceinline__ void split_store4(char* dh, char* dl, float4 v) {
    __nv_bfloat16 h0 = __float2bfloat16(v.x);
    __nv_bfloat16 h1 = __float2bfloat16(v.y);
    __nv_bfloat16 h2 = __float2bfloat16(v.z);
    __nv_bfloat16 h3 = __float2bfloat16(v.w);
    __nv_bfloat162 hp0; hp0.x = h0; hp0.y = h1;
    __nv_bfloat162 hp1; hp1.x = h2; hp1.y = h3;
    *(__nv_bfloat162*)(dh)     = hp0;
    *(__nv_bfloat162*)(dh + 4) = hp1;
    __nv_bfloat162 lp0, lp1;
    lp0.x = __float2bfloat16(v.x - __bfloat162float(h0));
    lp0.y = __float2bfloat16(v.y - __bfloat162float(h1));
    lp1.x = __float2bfloat16(v.z - __bfloat162float(h2));
    lp1.y = __float2bfloat16(v.w - __bfloat162float(h3));
    *(__nv_bfloat162*)(dl)     = lp0;
    *(__nv_bfloat162*)(dl + 4) = lp1;
}

// ---------------------------------------------------------------------------
// Kernel 1: packed in-projection via STAGED split-bf16 HMMA.
// C[4096 x 2304] = X_sel @ W^T + b (scaled) -> g_projh/l, g_v.
// CTA tile 128M x 64N, k-chunks of 32.  grid (36 ct, 32 rt), 256 thr.
// smem: Ah 10240 + Al 10240 + Bh 5120 + Bl 5120 = 30720 B.
// ---------------------------------------------------------------------------
__global__ void __launch_bounds__(256) proj_hmma_kernel(
        const float* __restrict__ xq, const float* __restrict__ xk,
        const float* __restrict__ xv, const float* __restrict__ W,
        const float* __restrict__ bias)
{
    extern __shared__ char smc[];
    char* SAh = smc;               // 128 rows x 80B
    char* SAl = smc + 10240;
    char* SBh = smc + 20480;       // 64 rows x 80B
    char* SBl = smc + 25600;
    int ct = blockIdx.x, rt = blockIdx.y;
    int j = ct >> 2;
    const float* X = (j == 2) ? xv
                   : ((j == 1 || j == 4 || j == 6 || j == 8) ? xk : xq);
    int t = threadIdx.x, lane = t & 31, w = t >> 5;
    int wm = w & 3, wn = w >> 2;

    unsigned sAh = s2u(SAh), sAl = s2u(SAl);
    float acc[2][4][4];
    #pragma unroll
    for (int a = 0; a < 2; a++)
        #pragma unroll
        for (int b = 0; b < 4; b++)
            #pragma unroll
            for (int c = 0; c < 4; c++) acc[a][b][c] = 0.f;

    const float* Xbase = X + (size_t)(rt * 128) * 256;
    const float* Wbase = W + (size_t)(ct * 64) * 256;

    #pragma unroll 1
    for (int ch = 0; ch < 8; ch++) {
        __syncthreads();
        // stage A: 128 x 32 fp32 -> hi/lo
        {
            int r = t >> 3, c = (t & 7) * 4;
            #pragma unroll
            for (int p = 0; p < 4; p++) {
                int rr = r + p * 32;
                float4 v = *(const float4*)(Xbase + (size_t)rr * 256 + ch * 32 + c);
                split_store4(SAh + rr * 80 + c * 2, SAl + rr * 80 + c * 2, v);
            }
            #pragma unroll
            for (int p = 0; p < 2; p++) {
                int rr = r + p * 32;
                float4 v = *(const float4*)(Wbase + (size_t)rr * 256 + ch * 32 + c);
                split_store4(SBh + rr * 80 + c * 2, SBl + rr * 80 + c * 2, v);
            }
        }
        __syncthreads();

        // A frags via ldmatrix
        unsigned ah[2][2][4], al[2][2][4];   // [rowtile][kstep][reg]
        #pragma unroll
        for (int rt2 = 0; rt2 < 2; rt2++) {
            unsigned off = (unsigned)((wm * 32 + rt2 * 16 + (lane & 15)) * 80
                                      + (lane >> 4) * 16);
            ldsm_x4(ah[rt2][0], sAh + off);
            ldsm_x4(ah[rt2][1], sAh + off + 32);
            ldsm_x4(al[rt2][0], sAl + off);
            ldsm_x4(al[rt2][1], sAl + off + 32);
        }
        // B frags via LDS + 3-term MMA
        #pragma unroll
        for (int g = 0; g < 4; g++) {
            int nr = wn * 32 + g * 8 + (lane >> 2);
            int cb = (lane & 3) * 4;
            #pragma unroll
            for (int ks = 0; ks < 2; ks++) {
                unsigned bh0 = *(const unsigned*)(SBh + nr * 80 + cb + ks * 32);
                unsigned bh1 = *(const unsigned*)(SBh + nr * 80 + cb + ks * 32 + 16);
                unsigned bl0 = *(const unsigned*)(SBl + nr * 80 + cb + ks * 32);
                unsigned bl1 = *(const unsigned*)(SBl + nr * 80 + cb + ks * 32 + 16);
                #pragma unroll
                for (int rt2 = 0; rt2 < 2; rt2++) {
                    mma_bf16(acc[rt2][g][0], acc[rt2][g][1], acc[rt2][g][2], acc[rt2][g][3],
                             ah[rt2][ks][0], ah[rt2][ks][1], ah[rt2][ks][2], ah[rt2][ks][3],
                             bh0, bh1);   // hi*hi
                    mma_bf16(acc[rt2][g][0], acc[rt2][g][1], acc[rt2][g][2], acc[rt2][g][3],
                             al[rt2][ks][0], al[rt2][ks][1], al[rt2][ks][2], al[rt2][ks][3],
                             bh0, bh1);   // lo*hi
                    mma_bf16(acc[rt2][g][0], acc[rt2][g][1], acc[rt2][g][2], acc[rt2][g][3],
                             ah[rt2][ks][0], ah[rt2][ks][1], ah[rt2][ks][2], ah[rt2][ks][3],
                             bl0, bl1);   // hi*lo
                }
            }
        }
    }

    // epilogue: bias + scale, scatter to head-major planes
    float scale = (j == 0 || j == 7) ? SCALING : 1.0f;
    #pragma unroll
    for (int rt2 = 0; rt2 < 2; rt2++) {
        int rbase = rt * 128 + wm * 32 + rt2 * 16 + (lane >> 2);
        #pragma unroll
        for (int g = 0; g < 4; g++) {
            int cbase = ct * 64 + wn * 32 + g * 8 + (lane & 3) * 2;
            #pragma unroll
            for (int e = 0; e < 4; e++) {
                int r = rbase + (e >> 1) * 8;      // d0,d1 -> r; d2,d3 -> r+8
                int col = cbase + (e & 1);
                float val = (acc[rt2][g][e] + bias[col]) * scale;
                int s = r >> 2, b = r & 3;
                int eo = col - j * 256;
                int bhp = b * 8 + (eo >> 5), dd = eo & 31;
                __nv_bfloat16 h = __float2bfloat16(val);
                g_projh[j][bhp][s][dd] = h;
                g_projl[j][bhp][s][dd] = __float2bfloat16(val - __bfloat162float(h));
                if (j == 2) g_v[bhp][s][dd] = val;
            }
        }
    }
}

// ---------------------------------------------------------------------------
// Kernel F1: per (bh, 8 rows): left/right logits (direct-LDG split-bf16 HMMA)
// -> softmax -> scans -> mask.  dyn smem 65536 B, 2 CTAs/SM  (R7-proven)
// ---------------------------------------------------------------------------
__global__ void __launch_bounds__(256, 2) f1_kernel()
{
    extern __shared__ float sm[];
    float* Ls = sm;
    float* Rs = sm + 8192;
    int t = threadIdx.x, lane = t & 31, w = t >> 5;
    int rt = blockIdx.x, bh = blockIdx.y;
    int row0 = rt * 8;
    int n = lane >> 2;
    int kq = (lane & 3) * 2;

    unsigned B[2][2][2][2];
    {
        const __nv_bfloat16* qh3 = &g_projh[3][bh][row0 + n][0];
        const __nv_bfloat16* ql3 = &g_projl[3][bh][row0 + n][0];
        const __nv_bfloat16* qh5 = &g_projh[5][bh][row0 + n][0];
        const __nv_bfloat16* ql5 = &g_projl[5][bh][row0 + n][0];
        B[0][0][0][0] = ldu32(qh3 + kq);      B[0][0][0][1] = ldu32(qh3 + kq + 8);
        B[0][0][1][0] = ldu32(qh3 + kq + 16); B[0][0][1][1] = ldu32(qh3 + kq + 24);
        B[0][1][0][0] = ldu32(ql3 + kq);      B[0][1][0][1] = ldu32(ql3 + kq + 8);
        B[0][1][1][0] = ldu32(ql3 + kq + 16); B[0][1][1][1] = ldu32(ql3 + kq + 24);
        B[1][0][0][0] = ldu32(qh5 + kq);      B[1][0][0][1] = ldu32(qh5 + kq + 8);
        B[1][0][1][0] = ldu32(qh5 + kq + 16); B[1][0][1][1] = ldu32(qh5 + kq + 24);
        B[1][1][0][0] = ldu32(ql5 + kq);      B[1][1][0][1] = ldu32(ql5 + kq + 8);
        B[1][1][1][0] = ldu32(ql5 + kq + 16); B[1][1][1][1] = ldu32(ql5 + kq + 24);
    }

    #pragma unroll 1
    for (int m = 0; m < 2; m++) {
        const __nv_bfloat16* Kh = &g_projh[m ? 6 : 4][bh][0][0];
        const __nv_bfloat16* Kl = &g_projl[m ? 6 : 4][bh][0][0];
        float* Obuf = m ? Rs : Ls;
        #pragma unroll 1
        for (int j = 0; j < 8; j++) {
            int col0 = (j * 8 + w) * 16;
            float d0 = 0.f, d1 = 0.f, d2 = 0.f, d3 = 0.f;
            #pragma unroll
            for (int ks = 0; ks < 2; ks++) {
                int off = ks * 16 + kq;
                const __nv_bfloat16* pa0 = Kh + (col0 + n) * 32 + off;
                const __nv_bfloat16* pa1 = Kh + (col0 + n + 8) * 32 + off;
                const __nv_bfloat16* pl0 = Kl + (col0 + n) * 32 + off;
                const __nv_bfloat16* pl1 = Kl + (col0 + n + 8) * 32 + off;
                unsigned ah0 = ldu32(pa0),     ah1 = ldu32(pa1);
                unsigned ah2 = ldu32(pa0 + 8), ah3 = ldu32(pa1 + 8);
                unsigned al0 = ldu32(pl0),     al1 = ldu32(pl1);
                unsigned al2 = ldu32(pl0 + 8), al3 = ldu32(pl1 + 8);
                mma_bf16(d0, d1, d2, d3, ah0, ah1, ah2, ah3,
                         B[m][0][ks][0], B[m][0][ks][1]);
                mma_bf16(d0, d1, d2, d3, al0, al1, al2, al3,
                         B[m][0][ks][0], B[m][0][ks][1]);
                mma_bf16(d0, d1, d2, d3, ah0, ah1, ah2, ah3,
                         B[m][1][ks][0], B[m][1][ks][1]);
            }
            int c = col0 + n;
            Obuf[kq * 1024 + c]           = d0;
            Obuf[(kq + 1) * 1024 + c]     = d1;
            Obuf[kq * 1024 + c + 8]       = d2;
            Obuf[(kq + 1) * 1024 + c + 8] = d3;
        }
    }
    __syncthreads();

    float* Lrow = Ls + w * 1024;
    float* Rrow = Rs + w * 1024;
    warp_softmax_row2(Lrow, Rrow, lane);

    float sL[32], sR[32];
    float runPL = 0.f, runPR = 0.f;
    #pragma unroll
    for (int q = 0; q < 32; q++) {
        float vL = Lrow[q * 32 + lane];
        float vR = Rrow[q * 32 + lane];
        float pL = vL, pR = vR;
        warp_iscan2(pL, pR, lane);
        float BL = __shfl_sync(0xffffffffu, pL, 31);
        float BR = __shfl_sync(0xffffffffu, pR, 31);
        runPL += pL;
        runPR += pR;
        Lrow[q * 32 + lane] = runPL;
        Rrow[q * 32 + lane] = runPR;
        sL[q] = BL - pL + vL;
        sR[q] = BR - pR + vR;
    }
    float* mout = &g_mask[bh][(size_t)(row0 + w) * 1024];
    float runSL = 0.f, runSR = 0.f;
    #pragma unroll
    for (int q = 31; q >= 0; q--) {
        runSL += sL[q];
        runSR += sR[q];
        mout[q * 32 + lane] = Lrow[q * 32 + lane] * runSR
                            + runSL * Rrow[q * 32 + lane];
    }
}

// ---------------------------------------------------------------------------
// Kernel F2: per (bh, 16 rows): global+local logits (direct-LDG HMMA) + mask
// combine -> softmax -> AV (SIMT fp32).  dyn smem 81920 B, 2 CTAs/SM (R7)
// ---------------------------------------------------------------------------
__global__ void __launch_bounds__(256, 2) f2_kernel()
{
    extern __shared__ float sm[];
    float* Cs = sm;
    float* Ps = sm + 16384;
    int t = threadIdx.x, lane = t & 31, w = t >> 5;
    int rt = blockIdx.x, bh = blockIdx.y;
    int row0 = rt * 16;
    int n = lane >> 2, kq = (lane & 3) * 2;

    unsigned B[2][2][2][2][2];
    #pragma unroll
    for (int mtx = 0; mtx < 2; mtx++) {
        int slice = mtx ? 7 : 0;
        #pragma unroll
        for (int rh = 0; rh < 2; rh++) {
            const __nv_bfloat16* qh = &g_projh[slice][bh][row0 + rh * 8 + n][0];
            const __nv_bfloat16* ql = &g_projl[slice][bh][row0 + rh * 8 + n][0];
            B[mtx][rh][0][0][0] = ldu32(qh + kq);      B[mtx][rh][0][0][1] = ldu32(qh + kq + 8);
            B[mtx][rh][0][1][0] = ldu32(qh + kq + 16); B[mtx][rh][0][1][1] = ldu32(qh + kq + 24);
            B[mtx][rh][1][0][0] = ldu32(ql + kq);      B[mtx][rh][1][0][1] = ldu32(ql + kq + 8);
            B[mtx][rh][1][1][0] = ldu32(ql + kq + 16); B[mtx][rh][1][1][1] = ldu32(ql + kq + 24);
        }
    }

    const __nv_bfloat16* K1h = &g_projh[1][bh][0][0];
    const __nv_bfloat16* K1l = &g_projl[1][bh][0][0];
    const __nv_bfloat16* K8h = &g_projh[8][bh][0][0];
    const __nv_bfloat16* K8l = &g_projl[8][bh][0][0];

    #pragma unroll 1
    for (int j = 0; j < 8; j++) {
        int col0 = (j * 8 + w) * 16;
        float g[8] = {}, lc[8] = {};
        #pragma unroll
        for (int ks = 0; ks < 2; ks++) {
            int off = ks * 16 + kq;
            const __nv_bfloat16* pa0 = K1h + (col0 + n) * 32 + off;
            const __nv_bfloat16* pa1 = K1h + (col0 + n + 8) * 32 + off;
            const __nv_bfloat16* pl0 = K1l + (col0 + n) * 32 + off;
            const __nv_bfloat16* pl1 = K1l + (col0 + n + 8) * 32 + off;
            unsigned ah0 = ldu32(pa0),     ah1 = ldu32(pa1);
            unsigned ah2 = ldu32(pa0 + 8), ah3 = ldu32(pa1 + 8);
            unsigned al0 = ldu32(pl0),     al1 = ldu32(pl1);
            unsigned al2 = ldu32(pl0 + 8), al3 = ldu32(pl1 + 8);
            #pragma unroll
            for (int rh = 0; rh < 2; rh++) {
                mma_bf16(g[rh*4+0], g[rh*4+1], g[rh*4+2], g[rh*4+3],
                         ah0, ah1, ah2, ah3, B[0][rh][0][ks][0], B[0][rh][0][ks][1]);
                mma_bf16(g[rh*4+0], g[rh*4+1], g[rh*4+2], g[rh*4+3],
                         al0, al1, al2, al3, B[0][rh][0][ks][0], B[0][rh][0][ks][1]);
                mma_bf16(g[rh*4+0], g[rh*4+1], g[rh*4+2], g[rh*4+3],
                         ah0, ah1, ah2, ah3, B[0][rh][1][ks][0], B[0][rh][1][ks][1]);
            }
        }
        #pragma unroll
        for (int ks = 0; ks < 2; ks++) {
            int off = ks * 16 + kq;
            const __nv_bfloat16* pa0 = K8h + (col0 + n) * 32 + off;
            const __nv_bfloat16* pa1 = K8h + (col0 + n + 8) * 32 + off;
            const __nv_bfloat16* pl0 = K8l + (col0 + n) * 32 + off;
            const __nv_bfloat16* pl1 = K8l + (col0 + n + 8) * 32 + off;
            unsigned ah0 = ldu32(pa0),     ah1 = ldu32(pa1);
            unsigned ah2 = ldu32(pa0 + 8), ah3 = ldu32(pa1 + 8);
            unsigned al0 = ldu32(pl0),     al1 = ldu32(pl1);
            unsigned al2 = ldu32(pl0 + 8), al3 = ldu32(pl1 + 8);
            #pragma unroll
            for (int rh = 0; rh < 2; rh++) {
                mma_bf16(lc[rh*4+0], lc[rh*4+1], lc[rh*4+2], lc[rh*4+3],
                         ah0, ah1, ah2, ah3, B[1][rh][0][ks][0], B[1][rh][0][ks][1]);
                mma_bf16(lc[rh*4+0], lc[rh*4+1], lc[rh*4+2], lc[rh*4+3],
                         al0, al1, al2, al3, B[1][rh][0][ks][0], B[1][rh][0][ks][1]);
                mma_bf16(lc[rh*4+0], lc[rh*4+1], lc[rh*4+2], lc[rh*4+3],
                         ah0, ah1, ah2, ah3, B[1][rh][1][ks][0], B[1][rh][1][ks][1]);
            }
        }
        int c = col0 + n;
        #pragma unroll
        for (int rh = 0; rh < 2; rh++) {
            int q = rh * 8 + kq;
            const float* mrow = &g_mask[bh][(size_t)(row0 + q) * 1024];
            float m0 = mrow[c], m1 = mrow[1024 + c];
            float m2 = mrow[c + 8], m3 = mrow[1024 + c + 8];
            Cs[q * 1024 + c]           = 0.1f * g[rh*4+0] + lc[rh*4+0] * m0;
            Cs[(q + 1) * 1024 + c]     = 0.1f * g[rh*4+1] + lc[rh*4+1] * m1;
            Cs[q * 1024 + c + 8]       = 0.1f * g[rh*4+2] + lc[rh*4+2] * m2;
            Cs[(q + 1) * 1024 + c + 8] = 0.1f * g[rh*4+3] + lc[rh*4+3] * m3;
        }
    }
    __syncthreads();

    warp_softmax_row2(Cs + w * 1024, Cs + (w + 8) * 1024, lane);
    __syncthreads();

    const float* Vsrc = &g_v[bh][0][0];
    int d = lane, jp = w;
    float acc[16];
    #pragma unroll
    for (int i = 0; i < 16; i++) acc[i] = 0.f;
    int base = jp * 128;
    #pragma unroll 2
    for (int jj = 0; jj < 128; jj += 4) {
        int j = base + jj;
        float v0 = Vsrc[(size_t)(j + 0) * 32 + d];
        float v1 = Vsrc[(size_t)(j + 1) * 32 + d];
        float v2 = Vsrc[(size_t)(j + 2) * 32 + d];
        float v3 = Vsrc[(size_t)(j + 3) * 32 + d];
        #pragma unroll
        for (int i = 0; i < 16; i++) {
            float4 c4 = *(const float4*)(Cs + i * 1024 + j);
            acc[i] += c4.x * v0 + c4.y * v1 + c4.z * v2 + c4.w * v3;
        }
    }
    #pragma unroll
    for (int i = 0; i < 16; i++) Ps[jp * 512 + i * 32 + d] = acc[i];
    __syncthreads();
    float s0 = 0.f, s1 = 0.f;
    #pragma unroll
    for (int p = 0; p < 8; p++) {
        s0 += Ps[p * 512 + w * 32 + lane];
        s1 += Ps[p * 512 + (w + 8) * 32 + lane];
    }
    int b = bh >> 3, hh = bh & 7;
    g_attn_pre[((row0 + w) * 4 + b) * 256 + hh * 32 + lane] = s0;
    g_attn_pre[((row0 + w + 8) * 4 + b) * 256 + hh * 32 + lane] = s1;
}

// ---------------------------------------------------------------------------
// Kernel 4: out-projection (scalar FFMA, R7-proven)
// ---------------------------------------------------------------------------
__global__ void __launch_bounds__(256) outproj_kernel(
        const float* __restrict__ W, const float* __restrict__ bias,
        float* __restrict__ out)
{
    __shared__ float As[16][68];
    __shared__ float Bs[16][68];
    int ct = blockIdx.x, rt = blockIdx.y;
    int t = threadIdx.x;
    int tx = t & 15, ty = t >> 4;
    int row0 = rt * 64, col0 = ct * 64;
    float acc[4][4] = {};
    for (int kt = 0; kt < 256; kt += 16) {
        #pragma unroll
        for (int l = 0; l < 4; l++) {
            int u = t + l * 256;
            int kk = u & 15, m = u >> 4;
            As[kk][m] = g_attn_pre[(row0 + m) * 256 + kt + kk];
            Bs[kk][m] = W[(col0 + m) * 256 + kt + kk];
        }
        __syncthreads();
        #pragma unroll
        for (int kk = 0; kk < 16; kk++) {
            float4 av = *(const float4*)(&As[kk][ty * 4]);
            float4 bv = *(const float4*)(&Bs[kk][tx * 4]);
            float a[4] = {av.x, av.y, av.z, av.w};
            float b[4] = {bv.x, bv.y, bv.z, bv.w};
            #pragma unroll
            for (int i = 0; i < 4; i++)
                #pragma unroll
                for (int c = 0; c < 4; c++)
                    acc[i][c] += a[i] * b[c];
        }
        __syncthreads();
    }
    #pragma unroll
    for (int i = 0; i < 4; i++) {
        int row = row0 + ty * 4 + i;
        #pragma unroll
        for (int c = 0; c < 4; c++) {
            int col = col0 + tx * 4 + c;
            out[row * 256 + col] = acc[i][c] + bias[col];
        }
    }
}

// ---------------------------------------------------------------------------
// Kernel 5: consistent_mask = sum over bh of g_mask (float4 vectorized)
// ---------------------------------------------------------------------------
__global__ void __launch_bounds__(256) mask_reduce_kernel(float* __restrict__ out)
{
    int i4 = (blockIdx.x * 256 + threadIdx.x) * 4;
    float4 s = {0.f, 0.f, 0.f, 0.f};
    #pragma unroll
    for (int bh = 0; bh < 32; bh++) {
        float4 v = *(const float4*)&g_mask[bh][i4];
        s.x += v.x; s.y += v.y; s.z += v.z; s.w += v.w;
    }
    *(float4*)(out + i4) = s;
}

// ---------------------------------------------------------------------------
extern "C" void kernel_launch(void* const* d_in, const int* in_sizes, int n_in,
                              void* d_out, int out_size)
{
    const float* q   = (const float*)d_in[0];
    const float* k   = (const float*)d_in[1];
    const float* v   = (const float*)d_in[2];
    const float* ipw = (const float*)d_in[3];
    const float* ipb = (const float*)d_in[4];
    const float* ow  = (const float*)d_in[5];
    const float* ob  = (const float*)d_in[6];
    float* out = (float*)d_out;

    cudaFuncSetAttribute(f1_kernel, cudaFuncAttributeMaxDynamicSharedMemorySize, 65536);
    cudaFuncSetAttribute(f2_kernel, cudaFuncAttributeMaxDynamicSharedMemorySize, 81920);

    proj_hmma_kernel<<<dim3(36, 32), 256, 30720>>>(q, k, v, ipw, ipb);
    f1_kernel<<<dim3(128, 32), 256, 65536>>>();
    f2_kernel<<<dim3(64, 32), 256, 81920>>>();
    outproj_kernel<<<dim3(4, 64), 256>>>(ow, ob, out);
    mask_reduce_kernel<<<1024, 256>>>(out + 1048576);
}

// round 11
// speedup vs baseline: 1.3560x; 1.0510x over previous
#include <cuda_runtime.h>
#include <cuda_bf16.h>

#define SCALING 0.17677669529663687f

// ---------------------------------------------------------------------------
// Scratch (static device globals — allowed; no runtime allocation)
// g_projp[j][bh][s][k]: .x = bf16x2 hi(dims 2k,2k+1), .y = bf16x2 lo
// ---------------------------------------------------------------------------
__device__ uint2 g_projp[9][32][1024][16];          // interleaved hi/lo planes
__device__ float g_v[32][1024][32];                 // V fp32 (AV)
__device__ float g_mask[32][1024 * 1024];           // local_mask
__device__ float g_attn_pre[4096 * 256];            // pre-out-proj fp32

// ---------------------------------------------------------------------------
// mma.sync m16n8k16 bf16 (HMMA), D/C fp32
// ---------------------------------------------------------------------------
__device__ __forceinline__ void mma_bf16(
    float& d0, float& d1, float& d2, float& d3,
    unsigned a0, unsigned a1, unsigned a2, unsigned a3,
    unsigned b0, unsigned b1)
{
    asm volatile(
        "mma.sync.aligned.m16n8k16.row.col.f32.bf16.bf16.f32 "
        "{%0,%1,%2,%3}, {%4,%5,%6,%7}, {%8,%9}, {%0,%1,%2,%3};\n"
        : "+f"(d0), "+f"(d1), "+f"(d2), "+f"(d3)
        : "r"(a0), "r"(a1), "r"(a2), "r"(a3), "r"(b0), "r"(b1));
}
__device__ __forceinline__ unsigned s2u(const void* p) {
    unsigned a;
    asm("{ .reg .u64 t; cvta.to.shared.u64 t, %1; cvt.u32.u64 %0, t; }"
        : "=r"(a) : "l"(p));
    return a;
}
__device__ __forceinline__ void ldsm_x4(unsigned r[4], unsigned addr) {
    asm volatile("ldmatrix.sync.aligned.m8n8.x4.shared.b16 {%0,%1,%2,%3}, [%4];"
        : "=r"(r[0]), "=r"(r[1]), "=r"(r[2]), "=r"(r[3]) : "r"(addr));
}
__device__ __forceinline__ unsigned packbf2(__nv_bfloat16 a, __nv_bfloat16 b) {
    __nv_bfloat162 p; p.x = a; p.y = b;
    return *(unsigned*)&p;
}

// ---------------------------------------------------------------------------
// warp helpers (R6-proven)
// ---------------------------------------------------------------------------
__device__ __forceinline__ void warp_iscan2(float& a, float& b, int lane) {
    #pragma unroll
    for (int o = 1; o < 32; o <<= 1) {
        float ua = __shfl_up_sync(0xffffffffu, a, o);
        float ub = __shfl_up_sync(0xffffffffu, b, o);
        if (lane >= o) { a += ua; b += ub; }
    }
}
__device__ __forceinline__ void warp_softmax_row2(float* r0, float* r1, int lane) {
    float m0 = -1e30f, m1 = -1e30f;
    #pragma unroll
    for (int q = 0; q < 32; q++) {
        m0 = fmaxf(m0, r0[q * 32 + lane]);
        m1 = fmaxf(m1, r1[q * 32 + lane]);
    }
    #pragma unroll
    for (int o = 16; o; o >>= 1) {
        m0 = fmaxf(m0, __shfl_xor_sync(0xffffffffu, m0, o));
        m1 = fmaxf(m1, __shfl_xor_sync(0xffffffffu, m1, o));
    }
    float s0 = 0.f, s1 = 0.f;
    #pragma unroll
    for (int q = 0; q < 32; q++) {
        float e0 = __expf(r0[q * 32 + lane] - m0);
        float e1 = __expf(r1[q * 32 + lane] - m1);
        r0[q * 32 + lane] = e0;
        r1[q * 32 + lane] = e1;
        s0 += e0; s1 += e1;
    }
    #pragma unroll
    for (int o = 16; o; o >>= 1) {
        s0 += __shfl_xor_sync(0xffffffffu, s0, o);
        s1 += __shfl_xor_sync(0xffffffffu, s1, o);
    }
    float i0 = 1.0f / s0, i1 = 1.0f / s1;
    #pragma unroll
    for (int q = 0; q < 32; q++) {
        r0[q * 32 + lane] *= i0;
        r1[q * 32 + lane] *= i1;
    }
}

// ---------------------------------------------------------------------------
// convert helper: float4 -> 4 hi bf16 + 4 lo bf16 (smem staging)
// ---------------------------------------------------------------------------
__device__ __forceinline__ void split_store4(char* dh, char* dl, float4 v) {
    __nv_bfloat16 h0 = __float2bfloat16(v.x);
    __nv_bfloat16 h1 = __float2bfloat16(v.y);
    __nv_bfloat16 h2 = __float2bfloat16(v.z);
    __nv_bfloat16 h3 = __float2bfloat16(v.w);
    *(unsigned*)(dh)     = packbf2(h0, h1);
    *(unsigned*)(dh + 4) = packbf2(h2, h3);
    *(unsigned*)(dl)     = packbf2(__float2bfloat16(v.x - __bfloat162float(h0)),
                                   __float2bfloat16(v.y - __bfloat162float(h1)));
    *(unsigned*)(dl + 4) = packbf2(__float2bfloat16(v.z - __bfloat162float(h2)),
                                   __float2bfloat16(v.w - __bfloat162float(h3)));
}

// ===========================================================================
// Shared staged-HMMA GEMM body:  C[128 x 64] tile of  Xf32 @ Wf32^T
// smem: SAh 10240 + SAl 10240 + SBh 5120 + SBl 5120 = 30720 B
// Accumulators returned in acc[2][4][4] per warp (layout as R10).
// ===========================================================================
__device__ __forceinline__ void staged_hmma_128x64(
        const float* __restrict__ Xbase, const float* __restrict__ Wbase,
        char* smc, int t, int lane, int w, float acc[2][4][4])
{
    char* SAh = smc;
    char* SAl = smc + 10240;
    char* SBh = smc + 20480;
    char* SBl = smc + 25600;
    int wm = w & 3, wn = w >> 2;
    unsigned sAh = s2u(SAh), sAl = s2u(SAl);

    #pragma unroll
    for (int a = 0; a < 2; a++)
        #pragma unroll
        for (int b = 0; b < 4; b++)
            #pragma unroll
            for (int c = 0; c < 4; c++) acc[a][b][c] = 0.f;

    #pragma unroll 1
    for (int ch = 0; ch < 8; ch++) {
        __syncthreads();
        {
            int r = t >> 3, c = (t & 7) * 4;
            #pragma unroll
            for (int p = 0; p < 4; p++) {
                int rr = r + p * 32;
                float4 v = *(const float4*)(Xbase + (size_t)rr * 256 + ch * 32 + c);
                split_store4(SAh + rr * 80 + c * 2, SAl + rr * 80 + c * 2, v);
            }
            #pragma unroll
            for (int p = 0; p < 2; p++) {
                int rr = r + p * 32;
                float4 v = *(const float4*)(Wbase + (size_t)rr * 256 + ch * 32 + c);
                split_store4(SBh + rr * 80 + c * 2, SBl + rr * 80 + c * 2, v);
            }
        }
        __syncthreads();

        unsigned ah[2][2][4], al[2][2][4];
        #pragma unroll
        for (int rt2 = 0; rt2 < 2; rt2++) {
            unsigned off = (unsigned)((wm * 32 + rt2 * 16 + (lane & 15)) * 80
                                      + (lane >> 4) * 16);
            ldsm_x4(ah[rt2][0], sAh + off);
            ldsm_x4(ah[rt2][1], sAh + off + 32);
            ldsm_x4(al[rt2][0], sAl + off);
            ldsm_x4(al[rt2][1], sAl + off + 32);
        }
        #pragma unroll
        for (int g = 0; g < 4; g++) {
            int nr = wn * 32 + g * 8 + (lane >> 2);
            int cb = (lane & 3) * 4;
            #pragma unroll
            for (int ks = 0; ks < 2; ks++) {
                unsigned bh0 = *(const unsigned*)(SBh + nr * 80 + cb + ks * 32);
                unsigned bh1 = *(const unsigned*)(SBh + nr * 80 + cb + ks * 32 + 16);
                unsigned bl0 = *(const unsigned*)(SBl + nr * 80 + cb + ks * 32);
                unsigned bl1 = *(const unsigned*)(SBl + nr * 80 + cb + ks * 32 + 16);
                #pragma unroll
                for (int rt2 = 0; rt2 < 2; rt2++) {
                    mma_bf16(acc[rt2][g][0], acc[rt2][g][1], acc[rt2][g][2], acc[rt2][g][3],
                             ah[rt2][ks][0], ah[rt2][ks][1], ah[rt2][ks][2], ah[rt2][ks][3],
                             bh0, bh1);
                    mma_bf16(acc[rt2][g][0], acc[rt2][g][1], acc[rt2][g][2], acc[rt2][g][3],
                             al[rt2][ks][0], al[rt2][ks][1], al[rt2][ks][2], al[rt2][ks][3],
                             bh0, bh1);
                    mma_bf16(acc[rt2][g][0], acc[rt2][g][1], acc[rt2][g][2], acc[rt2][g][3],
                             ah[rt2][ks][0], ah[rt2][ks][1], ah[rt2][ks][2], ah[rt2][ks][3],
                             bl0, bl1);
                }
            }
        }
    }
}

// ---------------------------------------------------------------------------
// Kernel 1: packed in-projection (staged HMMA) -> interleaved planes + g_v
// grid (36 ct, 32 rt), 256 thr, smem 30720
// ---------------------------------------------------------------------------
__global__ void __launch_bounds__(256) proj_hmma_kernel(
        const float* __restrict__ xq, const float* __restrict__ xk,
        const float* __restrict__ xv, const float* __restrict__ W,
        const float* __restrict__ bias)
{
    extern __shared__ char smc[];
    int ct = blockIdx.x, rt = blockIdx.y;
    int j = ct >> 2;
    const float* X = (j == 2) ? xv
                   : ((j == 1 || j == 4 || j == 6 || j == 8) ? xk : xq);
    int t = threadIdx.x, lane = t & 31, w = t >> 5;
    int wm = w & 3, wn = w >> 2;

    float acc[2][4][4];
    staged_hmma_128x64(X + (size_t)(rt * 128) * 256,
                       W + (size_t)(ct * 64) * 256, smc, t, lane, w, acc);

    float scale = (j == 0 || j == 7) ? SCALING : 1.0f;
    #pragma unroll
    for (int rt2 = 0; rt2 < 2; rt2++) {
        int rbase = rt * 128 + wm * 32 + rt2 * 16 + (lane >> 2);
        #pragma unroll
        for (int g = 0; g < 4; g++) {
            int cbase = ct * 64 + wn * 32 + g * 8 + (lane & 3) * 2;
            int eo = cbase - j * 256;            // even
            #pragma unroll
            for (int half = 0; half < 2; half++) {
                int r = rbase + half * 8;
                float v0 = (acc[rt2][g][half * 2 + 0] + bias[cbase]) * scale;
                float v1 = (acc[rt2][g][half * 2 + 1] + bias[cbase + 1]) * scale;
                int s = r >> 2, b = r & 3;
                int bhp = b * 8 + (eo >> 5), dd = eo & 31;
                __nv_bfloat16 h0 = __float2bfloat16(v0);
                __nv_bfloat16 h1 = __float2bfloat16(v1);
                uint2 val;
                val.x = packbf2(h0, h1);
                val.y = packbf2(__float2bfloat16(v0 - __bfloat162float(h0)),
                                __float2bfloat16(v1 - __bfloat162float(h1)));
                g_projp[j][bhp][s][dd >> 1] = val;
                if (j == 2) *(float2*)&g_v[bhp][s][dd] = make_float2(v0, v1);
            }
        }
    }
}

// ---------------------------------------------------------------------------
// Kernel F1: per (bh, 8 rows): left/right logits (uint2 direct-LDG HMMA)
// -> softmax -> scans -> mask.  dyn smem 65536 B, 2 CTAs/SM
// ---------------------------------------------------------------------------
__global__ void __launch_bounds__(256, 2) f1_kernel()
{
    extern __shared__ float sm[];
    float* Ls = sm;
    float* Rs = sm + 8192;
    int t = threadIdx.x, lane = t & 31, w = t >> 5;
    int rt = blockIdx.x, bh = blockIdx.y;
    int row0 = rt * 8;
    int n = lane >> 2;
    int pi = (lane & 3);         // pair index base: dims (2*pi, 2*pi+1)

    // B-frags: [mtx][hi/lo][kstep][reg]
    unsigned B[2][2][2][2];
    #pragma unroll
    for (int m = 0; m < 2; m++) {
        const uint2* qp = g_projp[m ? 5 : 3][bh][row0 + n];
        uint2 u0 = qp[pi],     u1 = qp[pi + 4];
        uint2 u2 = qp[pi + 8], u3 = qp[pi + 12];
        B[m][0][0][0] = u0.x; B[m][1][0][0] = u0.y;
        B[m][0][0][1] = u1.x; B[m][1][0][1] = u1.y;
        B[m][0][1][0] = u2.x; B[m][1][1][0] = u2.y;
        B[m][0][1][1] = u3.x; B[m][1][1][1] = u3.y;
    }

    #pragma unroll 1
    for (int m = 0; m < 2; m++) {
        const uint2* Kp = &g_projp[m ? 6 : 4][bh][0][0];
        float* Obuf = m ? Rs : Ls;
        #pragma unroll 1
        for (int j = 0; j < 8; j++) {
            int col0 = (j * 8 + w) * 16;
            const uint2* r0p = Kp + (size_t)(col0 + n) * 16;
            const uint2* r1p = Kp + (size_t)(col0 + n + 8) * 16;
            float d0 = 0.f, d1 = 0.f, d2 = 0.f, d3 = 0.f;
            #pragma unroll
            for (int ks = 0; ks < 2; ks++) {
                int ip = ks * 8 + pi;
                uint2 a0 = r0p[ip],     a1 = r1p[ip];
                uint2 a2 = r0p[ip + 4], a3 = r1p[ip + 4];
                mma_bf16(d0, d1, d2, d3, a0.x, a1.x, a2.x, a3.x,
                         B[m][0][ks][0], B[m][0][ks][1]);   // hi*hi
                mma_bf16(d0, d1, d2, d3, a0.y, a1.y, a2.y, a3.y,
                         B[m][0][ks][0], B[m][0][ks][1]);   // lo*hi
                mma_bf16(d0, d1, d2, d3, a0.x, a1.x, a2.x, a3.x,
                         B[m][1][ks][0], B[m][1][ks][1]);   // hi*lo
            }
            int c = col0 + n;
            int kq = pi * 2;
            Obuf[kq * 1024 + c]           = d0;
            Obuf[(kq + 1) * 1024 + c]     = d1;
            Obuf[kq * 1024 + c + 8]       = d2;
            Obuf[(kq + 1) * 1024 + c + 8] = d3;
        }
    }
    __syncthreads();

    // ---- softmax + 2-level prefix/suffix -> mask (R6-proven) --------------
    float* Lrow = Ls + w * 1024;
    float* Rrow = Rs + w * 1024;
    warp_softmax_row2(Lrow, Rrow, lane);

    float sL[32], sR[32];
    float runPL = 0.f, runPR = 0.f;
    #pragma unroll
    for (int q = 0; q < 32; q++) {
        float vL = Lrow[q * 32 + lane];
        float vR = Rrow[q * 32 + lane];
        float pL = vL, pR = vR;
        warp_iscan2(pL, pR, lane);
        float BL = __shfl_sync(0xffffffffu, pL, 31);
        float BR = __shfl_sync(0xffffffffu, pR, 31);
        runPL += pL;
        runPR += pR;
        Lrow[q * 32 + lane] = runPL;
        Rrow[q * 32 + lane] = runPR;
        sL[q] = BL - pL + vL;
        sR[q] = BR - pR + vR;
    }
    float* mout = &g_mask[bh][(size_t)(row0 + w) * 1024];
    float runSL = 0.f, runSR = 0.f;
    #pragma unroll
    for (int q = 31; q >= 0; q--) {
        runSL += sL[q];
        runSR += sR[q];
        mout[q * 32 + lane] = Lrow[q * 32 + lane] * runSR
                            + runSL * Rrow[q * 32 + lane];
    }
}

// ---------------------------------------------------------------------------
// Kernel F2: per (bh, 16 rows): global+local logits (uint2 direct-LDG HMMA)
// + mask combine -> softmax -> AV (SIMT fp32).  dyn smem 81920 B, 2 CTAs/SM
// ---------------------------------------------------------------------------
__global__ void __launch_bounds__(256, 2) f2_kernel()
{
    extern __shared__ float sm[];
    float* Cs = sm;
    float* Ps = sm + 16384;
    int t = threadIdx.x, lane = t & 31, w = t >> 5;
    int rt = blockIdx.x, bh = blockIdx.y;
    int row0 = rt * 16;
    int n = lane >> 2, pi = lane & 3;

    // B-frags: [mtx][rowhalf][hi/lo][kstep][reg]
    unsigned B[2][2][2][2][2];
    #pragma unroll
    for (int mtx = 0; mtx < 2; mtx++) {
        int slice = mtx ? 7 : 0;
        #pragma unroll
        for (int rh = 0; rh < 2; rh++) {
            const uint2* qp = g_projp[slice][bh][row0 + rh * 8 + n];
            uint2 u0 = qp[pi],     u1 = qp[pi + 4];
            uint2 u2 = qp[pi + 8], u3 = qp[pi + 12];
            B[mtx][rh][0][0][0] = u0.x; B[mtx][rh][1][0][0] = u0.y;
            B[mtx][rh][0][0][1] = u1.x; B[mtx][rh][1][0][1] = u1.y;
            B[mtx][rh][0][1][0] = u2.x; B[mtx][rh][1][1][0] = u2.y;
            B[mtx][rh][0][1][1] = u3.x; B[mtx][rh][1][1][1] = u3.y;
        }
    }

    const uint2* K1 = &g_projp[1][bh][0][0];
    const uint2* K8 = &g_projp[8][bh][0][0];

    #pragma unroll 1
    for (int j = 0; j < 8; j++) {
        int col0 = (j * 8 + w) * 16;
        float g[8] = {}, lc[8] = {};
        // ---- global logits: K1 ----
        {
            const uint2* r0p = K1 + (size_t)(col0 + n) * 16;
            const uint2* r1p = K1 + (size_t)(col0 + n + 8) * 16;
            #pragma unroll
            for (int ks = 0; ks < 2; ks++) {
                int ip = ks * 8 + pi;
                uint2 a0 = r0p[ip],     a1 = r1p[ip];
                uint2 a2 = r0p[ip + 4], a3 = r1p[ip + 4];
                #pragma unroll
                for (int rh = 0; rh < 2; rh++) {
                    mma_bf16(g[rh*4+0], g[rh*4+1], g[rh*4+2], g[rh*4+3],
                             a0.x, a1.x, a2.x, a3.x,
                             B[0][rh][0][ks][0], B[0][rh][0][ks][1]);
                    mma_bf16(g[rh*4+0], g[rh*4+1], g[rh*4+2], g[rh*4+3],
                             a0.y, a1.y, a2.y, a3.y,
                             B[0][rh][0][ks][0], B[0][rh][0][ks][1]);
                    mma_bf16(g[rh*4+0], g[rh*4+1], g[rh*4+2], g[rh*4+3],
                             a0.x, a1.x, a2.x, a3.x,
                             B[0][rh][1][ks][0], B[0][rh][1][ks][1]);
                }
            }
        }
        // ---- local logits: K8 ----
        {
            const uint2* r0p = K8 + (size_t)(col0 + n) * 16;
            const uint2* r1p = K8 + (size_t)(col0 + n + 8) * 16;
            #pragma unroll
            for (int ks = 0; ks < 2; ks++) {
                int ip = ks * 8 + pi;
                uint2 a0 = r0p[ip],     a1 = r1p[ip];
                uint2 a2 = r0p[ip + 4], a3 = r1p[ip + 4];
                #pragma unroll
                for (int rh = 0; rh < 2; rh++) {
                    mma_bf16(lc[rh*4+0], lc[rh*4+1], lc[rh*4+2], lc[rh*4+3],
                             a0.x, a1.x, a2.x, a3.x,
                             B[1][rh][0][ks][0], B[1][rh][0][ks][1]);
                    mma_bf16(lc[rh*4+0], lc[rh*4+1], lc[rh*4+2], lc[rh*4+3],
                             a0.y, a1.y, a2.y, a3.y,
                             B[1][rh][0][ks][0], B[1][rh][0][ks][1]);
                    mma_bf16(lc[rh*4+0], lc[rh*4+1], lc[rh*4+2], lc[rh*4+3],
                             a0.x, a1.x, a2.x, a3.x,
                             B[1][rh][1][ks][0], B[1][rh][1][ks][1]);
                }
            }
        }
        // ---- combine with mask and store ----
        int c = col0 + n;
        int kq = pi * 2;
        #pragma unroll
        for (int rh = 0; rh < 2; rh++) {
            int q = rh * 8 + kq;
            const float* mrow = &g_mask[bh][(size_t)(row0 + q) * 1024];
            float m0 = mrow[c], m1 = mrow[1024 + c];
            float m2 = mrow[c + 8], m3 = mrow[1024 + c + 8];
            Cs[q * 1024 + c]           = 0.1f * g[rh*4+0] + lc[rh*4+0] * m0;
            Cs[(q + 1) * 1024 + c]     = 0.1f * g[rh*4+1] + lc[rh*4+1] * m1;
            Cs[q * 1024 + c + 8]       = 0.1f * g[rh*4+2] + lc[rh*4+2] * m2;
            Cs[(q + 1) * 1024 + c + 8] = 0.1f * g[rh*4+3] + lc[rh*4+3] * m3;
        }
    }
    __syncthreads();

    warp_softmax_row2(Cs + w * 1024, Cs + (w + 8) * 1024, lane);
    __syncthreads();

    // ---- AV: thread (d=lane, jp=w) owns j-slice [128w, 128w+128) ----------
    const float* Vsrc = &g_v[bh][0][0];
    int d = lane, jp = w;
    float acc[16];
    #pragma unroll
    for (int i = 0; i < 16; i++) acc[i] = 0.f;
    int base = jp * 128;
    #pragma unroll 2
    for (int jj = 0; jj < 128; jj += 4) {
        int j = base + jj;
        float v0 = Vsrc[(size_t)(j + 0) * 32 + d];
        float v1 = Vsrc[(size_t)(j + 1) * 32 + d];
        float v2 = Vsrc[(size_t)(j + 2) * 32 + d];
        float v3 = Vsrc[(size_t)(j + 3) * 32 + d];
        #pragma unroll
        for (int i = 0; i < 16; i++) {
            float4 c4 = *(const float4*)(Cs + i * 1024 + j);
            acc[i] += c4.x * v0 + c4.y * v1 + c4.z * v2 + c4.w * v3;
        }
    }
    #pragma unroll
    for (int i = 0; i < 16; i++) Ps[jp * 512 + i * 32 + d] = acc[i];
    __syncthreads();
    float s0 = 0.f, s1 = 0.f;
    #pragma unroll
    for (int p = 0; p < 8; p++) {
        s0 += Ps[p * 512 + w * 32 + lane];
        s1 += Ps[p * 512 + (w + 8) * 32 + lane];
    }
    int b = bh >> 3, hh = bh & 7;
    g_attn_pre[((row0 + w) * 4 + b) * 256 + hh * 32 + lane] = s0;
    g_attn_pre[((row0 + w + 8) * 4 + b) * 256 + hh * 32 + lane] = s1;
}

// ---------------------------------------------------------------------------
// Kernel 4: out-projection via staged HMMA.  grid (4 ct, 32 rt), smem 30720
// ---------------------------------------------------------------------------
__global__ void __launch_bounds__(256) outproj_hmma_kernel(
        const float* __restrict__ W, const float* __restrict__ bias,
        float* __restrict__ out)
{
    extern __shared__ char smc[];
    int ct = blockIdx.x, rt = blockIdx.y;
    int t = threadIdx.x, lane = t & 31, w = t >> 5;
    int wm = w & 3, wn = w >> 2;

    float acc[2][4][4];
    staged_hmma_128x64(g_attn_pre + (size_t)(rt * 128) * 256,
                       W + (size_t)(ct * 64) * 256, smc, t, lane, w, acc);

    #pragma unroll
    for (int rt2 = 0; rt2 < 2; rt2++) {
        int rbase = rt * 128 + wm * 32 + rt2 * 16 + (lane >> 2);
        #pragma unroll
        for (int g = 0; g < 4; g++) {
            int cbase = ct * 64 + wn * 32 + g * 8 + (lane & 3) * 2;
            float b0 = bias[cbase], b1 = bias[cbase + 1];
            #pragma unroll
            for (int half = 0; half < 2; half++) {
                int r = rbase + half * 8;
                *(float2*)(out + (size_t)r * 256 + cbase) =
                    make_float2(acc[rt2][g][half * 2 + 0] + b0,
                                acc[rt2][g][half * 2 + 1] + b1);
            }
        }
    }
}

// ---------------------------------------------------------------------------
// Kernel 5: consistent_mask = sum over bh of g_mask (float4 vectorized)
// ---------------------------------------------------------------------------
__global__ void __launch_bounds__(256) mask_reduce_kernel(float* __restrict__ out)
{
    int i4 = (blockIdx.x * 256 + threadIdx.x) * 4;
    float4 s = {0.f, 0.f, 0.f, 0.f};
    #pragma unroll
    for (int bh = 0; bh < 32; bh++) {
        float4 v = *(const float4*)&g_mask[bh][i4];
        s.x += v.x; s.y += v.y; s.z += v.z; s.w += v.w;
    }
    *(float4*)(out + i4) = s;
}

// ---------------------------------------------------------------------------
extern "C" void kernel_launch(void* const* d_in, const int* in_sizes, int n_in,
                              void* d_out, int out_size)
{
    const float* q   = (const float*)d_in[0];
    const float* k   = (const float*)d_in[1];
    const float* v   = (const float*)d_in[2];
    const float* ipw = (const float*)d_in[3];
    const float* ipb = (const float*)d_in[4];
    const float* ow  = (const float*)d_in[5];
    const float* ob  = (const float*)d_in[6];
    float* out = (float*)d_out;

    cudaFuncSetAttribute(f1_kernel, cudaFuncAttributeMaxDynamicSharedMemorySize, 65536);
    cudaFuncSetAttribute(f2_kernel, cudaFuncAttributeMaxDynamicSharedMemorySize, 81920);

    proj_hmma_kernel<<<dim3(36, 32), 256, 30720>>>(q, k, v, ipw, ipb);
    f1_kernel<<<dim3(128, 32), 256, 65536>>>();
    f2_kernel<<<dim3(64, 32), 256, 81920>>>();
    outproj_hmma_kernel<<<dim3(4, 32), 256, 30720>>>(ow, ob, out);
    mask_reduce_kernel<<<1024, 256>>>(out + 1048576);
}

// round 12
// speedup vs baseline: 1.4482x; 1.0680x over previous
#include <cuda_runtime.h>
#include <cuda_bf16.h>

#define SCALING 0.17677669529663687f

// ---------------------------------------------------------------------------
// Scratch (static device globals — allowed; no runtime allocation)
// g_projp[j][bh][s][k]: .x = bf16x2 hi(dims 2k,2k+1), .y = bf16x2 lo
// ---------------------------------------------------------------------------
__device__ uint2 g_projp[9][32][1024][16];          // interleaved hi/lo planes
__device__ float g_v[32][1024][32];                 // V fp32 (AV)
__device__ float g_mask[32][1024 * 1024];           // local_mask
__device__ float g_attn_pre[4096 * 256];            // pre-out-proj fp32

// ---------------------------------------------------------------------------
// mma.sync m16n8k16 bf16 (HMMA), D/C fp32
// ---------------------------------------------------------------------------
__device__ __forceinline__ void mma_bf16(
    float& d0, float& d1, float& d2, float& d3,
    unsigned a0, unsigned a1, unsigned a2, unsigned a3,
    unsigned b0, unsigned b1)
{
    asm volatile(
        "mma.sync.aligned.m16n8k16.row.col.f32.bf16.bf16.f32 "
        "{%0,%1,%2,%3}, {%4,%5,%6,%7}, {%8,%9}, {%0,%1,%2,%3};\n"
        : "+f"(d0), "+f"(d1), "+f"(d2), "+f"(d3)
        : "r"(a0), "r"(a1), "r"(a2), "r"(a3), "r"(b0), "r"(b1));
}
__device__ __forceinline__ unsigned s2u(const void* p) {
    unsigned a;
    asm("{ .reg .u64 t; cvta.to.shared.u64 t, %1; cvt.u32.u64 %0, t; }"
        : "=r"(a) : "l"(p));
    return a;
}
__device__ __forceinline__ void ldsm_x4(unsigned r[4], unsigned addr) {
    asm volatile("ldmatrix.sync.aligned.m8n8.x4.shared.b16 {%0,%1,%2,%3}, [%4];"
        : "=r"(r[0]), "=r"(r[1]), "=r"(r[2]), "=r"(r[3]) : "r"(addr));
}
__device__ __forceinline__ unsigned packbf2(__nv_bfloat16 a, __nv_bfloat16 b) {
    __nv_bfloat162 p; p.x = a; p.y = b;
    return *(unsigned*)&p;
}

// ---------------------------------------------------------------------------
// warp helpers (R6-proven)
// ---------------------------------------------------------------------------
__device__ __forceinline__ void warp_iscan2(float& a, float& b, int lane) {
    #pragma unroll
    for (int o = 1; o < 32; o <<= 1) {
        float ua = __shfl_up_sync(0xffffffffu, a, o);
        float ub = __shfl_up_sync(0xffffffffu, b, o);
        if (lane >= o) { a += ua; b += ub; }
    }
}
__device__ __forceinline__ void warp_softmax_row2(float* r0, float* r1, int lane) {
    float m0 = -1e30f, m1 = -1e30f;
    #pragma unroll
    for (int q = 0; q < 32; q++) {
        m0 = fmaxf(m0, r0[q * 32 + lane]);
        m1 = fmaxf(m1, r1[q * 32 + lane]);
    }
    #pragma unroll
    for (int o = 16; o; o >>= 1) {
        m0 = fmaxf(m0, __shfl_xor_sync(0xffffffffu, m0, o));
        m1 = fmaxf(m1, __shfl_xor_sync(0xffffffffu, m1, o));
    }
    float s0 = 0.f, s1 = 0.f;
    #pragma unroll
    for (int q = 0; q < 32; q++) {
        float e0 = __expf(r0[q * 32 + lane] - m0);
        float e1 = __expf(r1[q * 32 + lane] - m1);
        r0[q * 32 + lane] = e0;
        r1[q * 32 + lane] = e1;
        s0 += e0; s1 += e1;
    }
    #pragma unroll
    for (int o = 16; o; o >>= 1) {
        s0 += __shfl_xor_sync(0xffffffffu, s0, o);
        s1 += __shfl_xor_sync(0xffffffffu, s1, o);
    }
    float i0 = 1.0f / s0, i1 = 1.0f / s1;
    #pragma unroll
    for (int q = 0; q < 32; q++) {
        r0[q * 32 + lane] *= i0;
        r1[q * 32 + lane] *= i1;
    }
}

// ---------------------------------------------------------------------------
// convert helper: float4 -> 4 hi bf16 + 4 lo bf16 (smem staging)
// ---------------------------------------------------------------------------
__device__ __forceinline__ void split_store4(char* dh, char* dl, float4 v) {
    __nv_bfloat16 h0 = __float2bfloat16(v.x);
    __nv_bfloat16 h1 = __float2bfloat16(v.y);
    __nv_bfloat16 h2 = __float2bfloat16(v.z);
    __nv_bfloat16 h3 = __float2bfloat16(v.w);
    *(unsigned*)(dh)     = packbf2(h0, h1);
    *(unsigned*)(dh + 4) = packbf2(h2, h3);
    *(unsigned*)(dl)     = packbf2(__float2bfloat16(v.x - __bfloat162float(h0)),
                                   __float2bfloat16(v.y - __bfloat162float(h1)));
    *(unsigned*)(dl + 4) = packbf2(__float2bfloat16(v.z - __bfloat162float(h2)),
                                   __float2bfloat16(v.w - __bfloat162float(h3)));
}

// ===========================================================================
// Shared staged-HMMA GEMM body:  C[128 x 64] tile of  Xf32 @ Wf32^T
// smem: SAh 10240 + SAl 10240 + SBh 5120 + SBl 5120 = 30720 B
// ===========================================================================
__device__ __forceinline__ void staged_hmma_128x64(
        const float* __restrict__ Xbase, const float* __restrict__ Wbase,
        char* smc, int t, int lane, int w, float acc[2][4][4])
{
    char* SAh = smc;
    char* SAl = smc + 10240;
    char* SBh = smc + 20480;
    char* SBl = smc + 25600;
    int wm = w & 3, wn = w >> 2;
    unsigned sAh = s2u(SAh), sAl = s2u(SAl);

    #pragma unroll
    for (int a = 0; a < 2; a++)
        #pragma unroll
        for (int b = 0; b < 4; b++)
            #pragma unroll
            for (int c = 0; c < 4; c++) acc[a][b][c] = 0.f;

    #pragma unroll 1
    for (int ch = 0; ch < 8; ch++) {
        __syncthreads();
        {
            int r = t >> 3, c = (t & 7) * 4;
            #pragma unroll
            for (int p = 0; p < 4; p++) {
                int rr = r + p * 32;
                float4 v = *(const float4*)(Xbase + (size_t)rr * 256 + ch * 32 + c);
                split_store4(SAh + rr * 80 + c * 2, SAl + rr * 80 + c * 2, v);
            }
            #pragma unroll
            for (int p = 0; p < 2; p++) {
                int rr = r + p * 32;
                float4 v = *(const float4*)(Wbase + (size_t)rr * 256 + ch * 32 + c);
                split_store4(SBh + rr * 80 + c * 2, SBl + rr * 80 + c * 2, v);
            }
        }
        __syncthreads();

        unsigned ah[2][2][4], al[2][2][4];
        #pragma unroll
        for (int rt2 = 0; rt2 < 2; rt2++) {
            unsigned off = (unsigned)((wm * 32 + rt2 * 16 + (lane & 15)) * 80
                                      + (lane >> 4) * 16);
            ldsm_x4(ah[rt2][0], sAh + off);
            ldsm_x4(ah[rt2][1], sAh + off + 32);
            ldsm_x4(al[rt2][0], sAl + off);
            ldsm_x4(al[rt2][1], sAl + off + 32);
        }
        #pragma unroll
        for (int g = 0; g < 4; g++) {
            int nr = wn * 32 + g * 8 + (lane >> 2);
            int cb = (lane & 3) * 4;
            #pragma unroll
            for (int ks = 0; ks < 2; ks++) {
                unsigned bh0 = *(const unsigned*)(SBh + nr * 80 + cb + ks * 32);
                unsigned bh1 = *(const unsigned*)(SBh + nr * 80 + cb + ks * 32 + 16);
                unsigned bl0 = *(const unsigned*)(SBl + nr * 80 + cb + ks * 32);
                unsigned bl1 = *(const unsigned*)(SBl + nr * 80 + cb + ks * 32 + 16);
                #pragma unroll
                for (int rt2 = 0; rt2 < 2; rt2++) {
                    mma_bf16(acc[rt2][g][0], acc[rt2][g][1], acc[rt2][g][2], acc[rt2][g][3],
                             ah[rt2][ks][0], ah[rt2][ks][1], ah[rt2][ks][2], ah[rt2][ks][3],
                             bh0, bh1);
                    mma_bf16(acc[rt2][g][0], acc[rt2][g][1], acc[rt2][g][2], acc[rt2][g][3],
                             al[rt2][ks][0], al[rt2][ks][1], al[rt2][ks][2], al[rt2][ks][3],
                             bh0, bh1);
                    mma_bf16(acc[rt2][g][0], acc[rt2][g][1], acc[rt2][g][2], acc[rt2][g][3],
                             ah[rt2][ks][0], ah[rt2][ks][1], ah[rt2][ks][2], ah[rt2][ks][3],
                             bl0, bl1);
                }
            }
        }
    }
}

// ---------------------------------------------------------------------------
// Kernel 1: packed in-projection (staged HMMA) -> interleaved planes + g_v
// ---------------------------------------------------------------------------
__global__ void __launch_bounds__(256) proj_hmma_kernel(
        const float* __restrict__ xq, const float* __restrict__ xk,
        const float* __restrict__ xv, const float* __restrict__ W,
        const float* __restrict__ bias)
{
    extern __shared__ char smc[];
    int ct = blockIdx.x, rt = blockIdx.y;
    int j = ct >> 2;
    const float* X = (j == 2) ? xv
                   : ((j == 1 || j == 4 || j == 6 || j == 8) ? xk : xq);
    int t = threadIdx.x, lane = t & 31, w = t >> 5;
    int wm = w & 3, wn = w >> 2;

    float acc[2][4][4];
    staged_hmma_128x64(X + (size_t)(rt * 128) * 256,
                       W + (size_t)(ct * 64) * 256, smc, t, lane, w, acc);

    float scale = (j == 0 || j == 7) ? SCALING : 1.0f;
    #pragma unroll
    for (int rt2 = 0; rt2 < 2; rt2++) {
        int rbase = rt * 128 + wm * 32 + rt2 * 16 + (lane >> 2);
        #pragma unroll
        for (int g = 0; g < 4; g++) {
            int cbase = ct * 64 + wn * 32 + g * 8 + (lane & 3) * 2;
            int eo = cbase - j * 256;
            #pragma unroll
            for (int half = 0; half < 2; half++) {
                int r = rbase + half * 8;
                float v0 = (acc[rt2][g][half * 2 + 0] + bias[cbase]) * scale;
                float v1 = (acc[rt2][g][half * 2 + 1] + bias[cbase + 1]) * scale;
                int s = r >> 2, b = r & 3;
                int bhp = b * 8 + (eo >> 5), dd = eo & 31;
                __nv_bfloat16 h0 = __float2bfloat16(v0);
                __nv_bfloat16 h1 = __float2bfloat16(v1);
                uint2 val;
                val.x = packbf2(h0, h1);
                val.y = packbf2(__float2bfloat16(v0 - __bfloat162float(h0)),
                                __float2bfloat16(v1 - __bfloat162float(h1)));
                g_projp[j][bhp][s][dd >> 1] = val;
                if (j == 2) *(float2*)&g_v[bhp][s][dd] = make_float2(v0, v1);
            }
        }
    }
}

// ---------------------------------------------------------------------------
// Kernel F1: per (bh, 16 rows), 512 threads / 16 warps:
// left/right logits (uint2 direct-LDG HMMA, two rowhalves) -> softmax ->
// scans -> mask.  dyn smem: Ls+Rs = 131072 B, 1 CTA/SM, 16 warps.
// Halves K L2 traffic vs the 8-row version (2048 CTAs instead of 4096).
// ---------------------------------------------------------------------------
__global__ void __launch_bounds__(512, 1) f1_kernel()
{
    extern __shared__ float sm[];
    float* Ls = sm;                  // 16 x 1024
    float* Rs = sm + 16384;          // 16 x 1024
    int t = threadIdx.x, lane = t & 31, w = t >> 5;   // w: 0..15
    int rt = blockIdx.x, bh = blockIdx.y;
    int row0 = rt * 16;
    int n = lane >> 2, pi = lane & 3;

    // B-frags: [mtx][rowhalf][hi/lo][kstep][reg]  (Q slices 3=left, 5=right)
    unsigned B[2][2][2][2][2];
    #pragma unroll
    for (int m = 0; m < 2; m++) {
        int slice = m ? 5 : 3;
        #pragma unroll
        for (int rh = 0; rh < 2; rh++) {
            const uint2* qp = g_projp[slice][bh][row0 + rh * 8 + n];
            uint2 u0 = qp[pi],     u1 = qp[pi + 4];
            uint2 u2 = qp[pi + 8], u3 = qp[pi + 12];
            B[m][rh][0][0][0] = u0.x; B[m][rh][1][0][0] = u0.y;
            B[m][rh][0][0][1] = u1.x; B[m][rh][1][0][1] = u1.y;
            B[m][rh][0][1][0] = u2.x; B[m][rh][1][1][0] = u2.y;
            B[m][rh][0][1][1] = u3.x; B[m][rh][1][1][1] = u3.y;
        }
    }

    #pragma unroll 1
    for (int m = 0; m < 2; m++) {
        const uint2* Kp = &g_projp[m ? 6 : 4][bh][0][0];
        float* Obuf = m ? Rs : Ls;
        #pragma unroll 1
        for (int j = 0; j < 4; j++) {
            int col0 = (j * 16 + w) * 16;
            const uint2* r0p = Kp + (size_t)(col0 + n) * 16;
            const uint2* r1p = Kp + (size_t)(col0 + n + 8) * 16;
            float d[2][4] = {};
            #pragma unroll
            for (int ks = 0; ks < 2; ks++) {
                int ip = ks * 8 + pi;
                uint2 a0 = r0p[ip],     a1 = r1p[ip];
                uint2 a2 = r0p[ip + 4], a3 = r1p[ip + 4];
                #pragma unroll
                for (int rh = 0; rh < 2; rh++) {
                    mma_bf16(d[rh][0], d[rh][1], d[rh][2], d[rh][3],
                             a0.x, a1.x, a2.x, a3.x,
                             B[m][rh][0][ks][0], B[m][rh][0][ks][1]);  // hi*hi
                    mma_bf16(d[rh][0], d[rh][1], d[rh][2], d[rh][3],
                             a0.y, a1.y, a2.y, a3.y,
                             B[m][rh][0][ks][0], B[m][rh][0][ks][1]);  // lo*hi
                    mma_bf16(d[rh][0], d[rh][1], d[rh][2], d[rh][3],
                             a0.x, a1.x, a2.x, a3.x,
                             B[m][rh][1][ks][0], B[m][rh][1][ks][1]);  // hi*lo
                }
            }
            int c = col0 + n;
            #pragma unroll
            for (int rh = 0; rh < 2; rh++) {
                int q = rh * 8 + pi * 2;
                Obuf[q * 1024 + c]           = d[rh][0];
                Obuf[(q + 1) * 1024 + c]     = d[rh][1];
                Obuf[q * 1024 + c + 8]       = d[rh][2];
                Obuf[(q + 1) * 1024 + c + 8] = d[rh][3];
            }
        }
    }
    __syncthreads();

    // ---- softmax + 2-level prefix/suffix -> mask (warp w owns row w) ------
    float* Lrow = Ls + w * 1024;
    float* Rrow = Rs + w * 1024;
    warp_softmax_row2(Lrow, Rrow, lane);

    float sL[32], sR[32];
    float runPL = 0.f, runPR = 0.f;
    #pragma unroll
    for (int q = 0; q < 32; q++) {
        float vL = Lrow[q * 32 + lane];
        float vR = Rrow[q * 32 + lane];
        float pL = vL, pR = vR;
        warp_iscan2(pL, pR, lane);
        float BL = __shfl_sync(0xffffffffu, pL, 31);
        float BR = __shfl_sync(0xffffffffu, pR, 31);
        runPL += pL;
        runPR += pR;
        Lrow[q * 32 + lane] = runPL;
        Rrow[q * 32 + lane] = runPR;
        sL[q] = BL - pL + vL;
        sR[q] = BR - pR + vR;
    }
    float* mout = &g_mask[bh][(size_t)(row0 + w) * 1024];
    float runSL = 0.f, runSR = 0.f;
    #pragma unroll
    for (int q = 31; q >= 0; q--) {
        runSL += sL[q];
        runSR += sR[q];
        mout[q * 32 + lane] = Lrow[q * 32 + lane] * runSR
                            + runSL * Rrow[q * 32 + lane];
    }
}

// ---------------------------------------------------------------------------
// Kernel F2: per (bh, 16 rows): global+local logits (uint2 direct-LDG HMMA)
// + mask combine -> softmax -> AV (SIMT fp32).  dyn smem 81920 B, 2 CTAs/SM
// (R11-verbatim)
// ---------------------------------------------------------------------------
__global__ void __launch_bounds__(256, 2) f2_kernel()
{
    extern __shared__ float sm[];
    float* Cs = sm;
    float* Ps = sm + 16384;
    int t = threadIdx.x, lane = t & 31, w = t >> 5;
    int rt = blockIdx.x, bh = blockIdx.y;
    int row0 = rt * 16;
    int n = lane >> 2, pi = lane & 3;

    unsigned B[2][2][2][2][2];
    #pragma unroll
    for (int mtx = 0; mtx < 2; mtx++) {
        int slice = mtx ? 7 : 0;
        #pragma unroll
        for (int rh = 0; rh < 2; rh++) {
            const uint2* qp = g_projp[slice][bh][row0 + rh * 8 + n];
            uint2 u0 = qp[pi],     u1 = qp[pi + 4];
            uint2 u2 = qp[pi + 8], u3 = qp[pi + 12];
            B[mtx][rh][0][0][0] = u0.x; B[mtx][rh][1][0][0] = u0.y;
            B[mtx][rh][0][0][1] = u1.x; B[mtx][rh][1][0][1] = u1.y;
            B[mtx][rh][0][1][0] = u2.x; B[mtx][rh][1][1][0] = u2.y;
            B[mtx][rh][0][1][1] = u3.x; B[mtx][rh][1][1][1] = u3.y;
        }
    }

    const uint2* K1 = &g_projp[1][bh][0][0];
    const uint2* K8 = &g_projp[8][bh][0][0];

    #pragma unroll 1
    for (int j = 0; j < 8; j++) {
        int col0 = (j * 8 + w) * 16;
        float g[8] = {}, lc[8] = {};
        {
            const uint2* r0p = K1 + (size_t)(col0 + n) * 16;
            const uint2* r1p = K1 + (size_t)(col0 + n + 8) * 16;
            #pragma unroll
            for (int ks = 0; ks < 2; ks++) {
                int ip = ks * 8 + pi;
                uint2 a0 = r0p[ip],     a1 = r1p[ip];
                uint2 a2 = r0p[ip + 4], a3 = r1p[ip + 4];
                #pragma unroll
                for (int rh = 0; rh < 2; rh++) {
                    mma_bf16(g[rh*4+0], g[rh*4+1], g[rh*4+2], g[rh*4+3],
                             a0.x, a1.x, a2.x, a3.x,
                             B[0][rh][0][ks][0], B[0][rh][0][ks][1]);
                    mma_bf16(g[rh*4+0], g[rh*4+1], g[rh*4+2], g[rh*4+3],
                             a0.y, a1.y, a2.y, a3.y,
                             B[0][rh][0][ks][0], B[0][rh][0][ks][1]);
                    mma_bf16(g[rh*4+0], g[rh*4+1], g[rh*4+2], g[rh*4+3],
                             a0.x, a1.x, a2.x, a3.x,
                             B[0][rh][1][ks][0], B[0][rh][1][ks][1]);
                }
            }
        }
        {
            const uint2* r0p = K8 + (size_t)(col0 + n) * 16;
            const uint2* r1p = K8 + (size_t)(col0 + n + 8) * 16;
            #pragma unroll
            for (int ks = 0; ks < 2; ks++) {
                int ip = ks * 8 + pi;
                uint2 a0 = r0p[ip],     a1 = r1p[ip];
                uint2 a2 = r0p[ip + 4], a3 = r1p[ip + 4];
                #pragma unroll
                for (int rh = 0; rh < 2; rh++) {
                    mma_bf16(lc[rh*4+0], lc[rh*4+1], lc[rh*4+2], lc[rh*4+3],
                             a0.x, a1.x, a2.x, a3.x,
                             B[1][rh][0][ks][0], B[1][rh][0][ks][1]);
                    mma_bf16(lc[rh*4+0], lc[rh*4+1], lc[rh*4+2], lc[rh*4+3],
                             a0.y, a1.y, a2.y, a3.y,
                             B[1][rh][0][ks][0], B[1][rh][0][ks][1]);
                    mma_bf16(lc[rh*4+0], lc[rh*4+1], lc[rh*4+2], lc[rh*4+3],
                             a0.x, a1.x, a2.x, a3.x,
                             B[1][rh][1][ks][0], B[1][rh][1][ks][1]);
                }
            }
        }
        int c = col0 + n;
        int kq = pi * 2;
        #pragma unroll
        for (int rh = 0; rh < 2; rh++) {
            int q = rh * 8 + kq;
            const float* mrow = &g_mask[bh][(size_t)(row0 + q) * 1024];
            float m0 = mrow[c], m1 = mrow[1024 + c];
            float m2 = mrow[c + 8], m3 = mrow[1024 + c + 8];
            Cs[q * 1024 + c]           = 0.1f * g[rh*4+0] + lc[rh*4+0] * m0;
            Cs[(q + 1) * 1024 + c]     = 0.1f * g[rh*4+1] + lc[rh*4+1] * m1;
            Cs[q * 1024 + c + 8]       = 0.1f * g[rh*4+2] + lc[rh*4+2] * m2;
            Cs[(q + 1) * 1024 + c + 8] = 0.1f * g[rh*4+3] + lc[rh*4+3] * m3;
        }
    }
    __syncthreads();

    warp_softmax_row2(Cs + w * 1024, Cs + (w + 8) * 1024, lane);
    __syncthreads();

    const float* Vsrc = &g_v[bh][0][0];
    int d = lane, jp = w;
    float acc[16];
    #pragma unroll
    for (int i = 0; i < 16; i++) acc[i] = 0.f;
    int base = jp * 128;
    #pragma unroll 2
    for (int jj = 0; jj < 128; jj += 4) {
        int j = base + jj;
        float v0 = Vsrc[(size_t)(j + 0) * 32 + d];
        float v1 = Vsrc[(size_t)(j + 1) * 32 + d];
        float v2 = Vsrc[(size_t)(j + 2) * 32 + d];
        float v3 = Vsrc[(size_t)(j + 3) * 32 + d];
        #pragma unroll
        for (int i = 0; i < 16; i++) {
            float4 c4 = *(const float4*)(Cs + i * 1024 + j);
            acc[i] += c4.x * v0 + c4.y * v1 + c4.z * v2 + c4.w * v3;
        }
    }
    #pragma unroll
    for (int i = 0; i < 16; i++) Ps[jp * 512 + i * 32 + d] = acc[i];
    __syncthreads();
    float s0 = 0.f, s1 = 0.f;
    #pragma unroll
    for (int p = 0; p < 8; p++) {
        s0 += Ps[p * 512 + w * 32 + lane];
        s1 += Ps[p * 512 + (w + 8) * 32 + lane];
    }
    int b = bh >> 3, hh = bh & 7;
    g_attn_pre[((row0 + w) * 4 + b) * 256 + hh * 32 + lane] = s0;
    g_attn_pre[((row0 + w + 8) * 4 + b) * 256 + hh * 32 + lane] = s1;
}

// ---------------------------------------------------------------------------
// Kernel 4: out-projection via staged HMMA (R11-proven)
// ---------------------------------------------------------------------------
__global__ void __launch_bounds__(256) outproj_hmma_kernel(
        const float* __restrict__ W, const float* __restrict__ bias,
        float* __restrict__ out)
{
    extern __shared__ char smc[];
    int ct = blockIdx.x, rt = blockIdx.y;
    int t = threadIdx.x, lane = t & 31, w = t >> 5;
    int wm = w & 3, wn = w >> 2;

    float acc[2][4][4];
    staged_hmma_128x64(g_attn_pre + (size_t)(rt * 128) * 256,
                       W + (size_t)(ct * 64) * 256, smc, t, lane, w, acc);

    #pragma unroll
    for (int rt2 = 0; rt2 < 2; rt2++) {
        int rbase = rt * 128 + wm * 32 + rt2 * 16 + (lane >> 2);
        #pragma unroll
        for (int g = 0; g < 4; g++) {
            int cbase = ct * 64 + wn * 32 + g * 8 + (lane & 3) * 2;
            float b0 = bias[cbase], b1 = bias[cbase + 1];
            #pragma unroll
            for (int half = 0; half < 2; half++) {
                int r = rbase + half * 8;
                *(float2*)(out + (size_t)r * 256 + cbase) =
                    make_float2(acc[rt2][g][half * 2 + 0] + b0,
                                acc[rt2][g][half * 2 + 1] + b1);
            }
        }
    }
}

// ---------------------------------------------------------------------------
// Kernel 5: consistent_mask = sum over bh of g_mask (float4 vectorized)
// ---------------------------------------------------------------------------
__global__ void __launch_bounds__(256) mask_reduce_kernel(float* __restrict__ out)
{
    int i4 = (blockIdx.x * 256 + threadIdx.x) * 4;
    float4 s = {0.f, 0.f, 0.f, 0.f};
    #pragma unroll
    for (int bh = 0; bh < 32; bh++) {
        float4 v = *(const float4*)&g_mask[bh][i4];
        s.x += v.x; s.y += v.y; s.z += v.z; s.w += v.w;
    }
    *(float4*)(out + i4) = s;
}

// ---------------------------------------------------------------------------
extern "C" void kernel_launch(void* const* d_in, const int* in_sizes, int n_in,
                              void* d_out, int out_size)
{
    const float* q   = (const float*)d_in[0];
    const float* k   = (const float*)d_in[1];
    const float* v   = (const float*)d_in[2];
    const float* ipw = (const float*)d_in[3];
    const float* ipb = (const float*)d_in[4];
    const float* ow  = (const float*)d_in[5];
    const float* ob  = (const float*)d_in[6];
    float* out = (float*)d_out;

    cudaFuncSetAttribute(f1_kernel, cudaFuncAttributeMaxDynamicSharedMemorySize, 131072);
    cudaFuncSetAttribute(f2_kernel, cudaFuncAttributeMaxDynamicSharedMemorySize, 81920);

    proj_hmma_kernel<<<dim3(36, 32), 256, 30720>>>(q, k, v, ipw, ipb);
    f1_kernel<<<dim3(64, 32), 512, 131072>>>();
    f2_kernel<<<dim3(64, 32), 256, 81920>>>();
    outproj_hmma_kernel<<<dim3(4, 32), 256, 30720>>>(ow, ob, out);
    mask_reduce_kernel<<<1024, 256>>>(out + 1048576);
}